// round 15
// baseline (speedup 1.0000x reference)
#include <cuda_runtime.h>
#include <cuda_bf16.h>
#include <math.h>
#include <stdint.h>

#define S_LEN   4096
#define D_MODEL 2048
#define NHEADS  16
#define HDIM    128

// ---------------------------------------------------------------------------
// Scratch (device globals: allocation-guard-safe)
// ---------------------------------------------------------------------------
__device__ __nv_bfloat16 g_xhi[S_LEN * D_MODEL];
__device__ __nv_bfloat16 g_xlo[S_LEN * D_MODEL];
__device__ __nv_bfloat16 g_qhi[S_LEN * D_MODEL];
__device__ __nv_bfloat16 g_qlo[S_LEN * D_MODEL];
__device__ __nv_bfloat16 g_khi[S_LEN * D_MODEL];
__device__ __nv_bfloat16 g_klo[S_LEN * D_MODEL];
__device__ __nv_bfloat16 g_vhi[S_LEN * D_MODEL];
__device__ __nv_bfloat16 g_vlo[S_LEN * D_MODEL];
__device__ __nv_bfloat16 g_ohi[S_LEN * D_MODEL];
__device__ __nv_bfloat16 g_olo[S_LEN * D_MODEL];
__device__ __nv_bfloat16 g_wqhi[D_MODEL * D_MODEL];
__device__ __nv_bfloat16 g_wqlo[D_MODEL * D_MODEL];
__device__ __nv_bfloat16 g_wkhi[D_MODEL * D_MODEL];
__device__ __nv_bfloat16 g_wklo[D_MODEL * D_MODEL];
__device__ __nv_bfloat16 g_wvhi[D_MODEL * D_MODEL];
__device__ __nv_bfloat16 g_wvlo[D_MODEL * D_MODEL];
__device__ __nv_bfloat16 g_wohi[D_MODEL * D_MODEL];
__device__ __nv_bfloat16 g_wolo[D_MODEL * D_MODEL];

// ---------------------------------------------------------------------------
// Helpers
// ---------------------------------------------------------------------------
__device__ __forceinline__ uint32_t smem_u32(const void* p) {
    uint32_t a;
    asm("{ .reg .u64 t; cvta.to.shared.u64 t, %1; cvt.u32.u64 %0, t; }" : "=r"(a) : "l"(p));
    return a;
}

#define LDSM_X4(r0, r1, r2, r3, addr)                                         \
    asm volatile("ldmatrix.sync.aligned.m8n8.x4.shared.b16 {%0,%1,%2,%3}, [%4];" \
        : "=r"(r0), "=r"(r1), "=r"(r2), "=r"(r3) : "r"(addr))

#define LDSM_X4_T(r0, r1, r2, r3, addr)                                       \
    asm volatile("ldmatrix.sync.aligned.m8n8.x4.trans.shared.b16 {%0,%1,%2,%3}, [%4];" \
        : "=r"(r0), "=r"(r1), "=r"(r2), "=r"(r3) : "r"(addr))

#define CP_ASYNC16(dst, src)                                                  \
    asm volatile("cp.async.cg.shared.global [%0], [%1], 16;" :: "r"(dst), "l"(src))
#define CP_COMMIT() asm volatile("cp.async.commit_group;" ::: "memory")
#define CP_WAIT0()  asm volatile("cp.async.wait_group 0;" ::: "memory")

__device__ __forceinline__ void mma_bf16(float& c0, float& c1, float& c2, float& c3,
                                         uint32_t a0, uint32_t a1, uint32_t a2, uint32_t a3,
                                         uint32_t b0, uint32_t b1) {
    asm volatile(
        "mma.sync.aligned.m16n8k16.row.col.f32.bf16.bf16.f32 "
        "{%0,%1,%2,%3}, {%4,%5,%6,%7}, {%8,%9}, {%0,%1,%2,%3};"
        : "+f"(c0), "+f"(c1), "+f"(c2), "+f"(c3)
        : "r"(a0), "r"(a1), "r"(a2), "r"(a3), "r"(b0), "r"(b1));
}

__device__ __forceinline__ uint32_t pack2(__nv_bfloat16 a, __nv_bfloat16 b) {
    __nv_bfloat162 t(a, b);
    return *reinterpret_cast<uint32_t*>(&t);
}

__device__ __forceinline__ void pack_hilo(float x, float y, uint32_t& hi, uint32_t& lo) {
    __nv_bfloat16 hx = __float2bfloat16(x), hy = __float2bfloat16(y);
    float rx = x - __bfloat162float(hx), ry = y - __bfloat162float(hy);
    hi = pack2(hx, hy);
    lo = pack2(__float2bfloat16(rx), __float2bfloat16(ry));
}

__device__ __forceinline__ float fast_exp2(float x) {
    float r;
    asm("ex2.approx.ftz.f32 %0, %1;" : "=f"(r) : "f"(x));
    return r;
}

__device__ __forceinline__ uint32_t swz64(uint32_t off) { return off ^ ((off >> 3) & 0x30); }
__device__ __forceinline__ uint32_t vswz(uint32_t off)  { return off ^ ((off >> 4) & 0x70); }

// ---------------------------------------------------------------------------
// fp32 -> bf16 hi/lo split, all 5 tensors fused into one launch.
// ---------------------------------------------------------------------------
__global__ __launch_bounds__(256) void split_all_kernel(
    const float4* __restrict__ x4,
    const float4* __restrict__ w0, const float4* __restrict__ w1,
    const float4* __restrict__ w2, const float4* __restrict__ w3,
    __nv_bfloat162* __restrict__ xh, __nv_bfloat162* __restrict__ xl,
    __nv_bfloat162* __restrict__ h0p, __nv_bfloat162* __restrict__ l0p,
    __nv_bfloat162* __restrict__ h1p, __nv_bfloat162* __restrict__ l1p,
    __nv_bfloat162* __restrict__ h2p, __nv_bfloat162* __restrict__ l2p,
    __nv_bfloat162* __restrict__ h3p, __nv_bfloat162* __restrict__ l3p,
    int nw4, int nx4)
{
    const int i = blockIdx.x * blockDim.x + threadIdx.x;
    const int s = blockIdx.y;
    const int n4 = (s == 4) ? nx4 : nw4;
    if (i >= n4) return;
    const float4* src = (s == 0) ? w0 : (s == 1) ? w1 : (s == 2) ? w2 : (s == 3) ? w3 : x4;
    __nv_bfloat162* hi = (s == 0) ? h0p : (s == 1) ? h1p : (s == 2) ? h2p : (s == 3) ? h3p : xh;
    __nv_bfloat162* lo = (s == 0) ? l0p : (s == 1) ? l1p : (s == 2) ? l2p : (s == 3) ? l3p : xl;
    float4 v = src[i];
    uint32_t a0, b0, a1, b1;
    pack_hilo(v.x, v.y, a0, b0);
    pack_hilo(v.z, v.w, a1, b1);
    *reinterpret_cast<uint32_t*>(&hi[2 * i + 0]) = a0;
    *reinterpret_cast<uint32_t*>(&hi[2 * i + 1]) = a1;
    *reinterpret_cast<uint32_t*>(&lo[2 * i + 0]) = b0;
    *reinterpret_cast<uint32_t*>(&lo[2 * i + 1]) = b1;
}

// ---------------------------------------------------------------------------
// bf16x3 GEMM, cp.async 2-stage (Round-9 champion config).
// ---------------------------------------------------------------------------
#define GBK2      32
#define GK_ITERS2 (D_MODEL / GBK2)
#define STAGE_B   32768
#define TO_AHI    0
#define TO_ALO    8192
#define TO_BHI    16384
#define TO_BLO    24576
#define GEMM_SMEM (2 * STAGE_B)   // 65536

template<bool BF16OUT>
__global__ __launch_bounds__(256) void gemm_mma_kernel(
    const __nv_bfloat16* __restrict__ Ahi, const __nv_bfloat16* __restrict__ Alo,
    const __nv_bfloat16* __restrict__ Bhi0, const __nv_bfloat16* __restrict__ Blo0,
    const __nv_bfloat16* __restrict__ Bhi1, const __nv_bfloat16* __restrict__ Blo1,
    const __nv_bfloat16* __restrict__ Bhi2, const __nv_bfloat16* __restrict__ Blo2,
    float* __restrict__ C0,
    __nv_bfloat16* __restrict__ Chi0, __nv_bfloat16* __restrict__ Clo0,
    __nv_bfloat16* __restrict__ Chi1, __nv_bfloat16* __restrict__ Clo1,
    __nv_bfloat16* __restrict__ Chi2, __nv_bfloat16* __restrict__ Clo2)
{
    extern __shared__ char smem[];
    const uint32_t sbase = smem_u32(smem);
    const int tid  = threadIdx.x;
    const int wid  = tid >> 5;
    const int lane = tid & 31;

    const __nv_bfloat16* Bhi = (blockIdx.z == 0) ? Bhi0 : (blockIdx.z == 1) ? Bhi1 : Bhi2;
    const __nv_bfloat16* Blo = (blockIdx.z == 0) ? Blo0 : (blockIdx.z == 1) ? Blo1 : Blo2;
    __nv_bfloat16* Chi = (blockIdx.z == 0) ? Chi0 : (blockIdx.z == 1) ? Chi1 : Chi2;
    __nv_bfloat16* Clo = (blockIdx.z == 0) ? Clo0 : (blockIdx.z == 1) ? Clo1 : Clo2;

    const int m0 = blockIdx.y * 128;
    const int n0 = blockIdx.x * 128;

    const int warp_m = wid & 1;
    const int warp_n = wid >> 1;

    const int lr0 = tid >> 2;
    const int lc0 = tid & 3;

    const uint32_t a_rowpart = (uint32_t)((warp_m * 64 + (lane & 15)) * 64 + (lane >> 4) * 16);
    const uint32_t b_rowpart = (uint32_t)((warp_n * 32 + (lane & 7) + ((lane >> 4) << 3)) * 64
                                          + ((lane >> 3) & 1) * 16);

    float acc[4][4][4];
#pragma unroll
    for (int i = 0; i < 4; i++)
#pragma unroll
        for (int j = 0; j < 4; j++)
#pragma unroll
            for (int t = 0; t < 4; t++) acc[i][j][t] = 0.0f;

    auto load_stage = [&](int it, int stage) {
        const int k0 = it * GBK2;
        const uint32_t sb = sbase + stage * STAGE_B;
        const __nv_bfloat16* srcs[4] = { Ahi, Alo, Bhi, Blo };
        const uint32_t offs[4] = { TO_AHI, TO_ALO, TO_BHI, TO_BLO };
        const int rows[4] = { m0, m0, n0, n0 };
#pragma unroll
        for (int t = 0; t < 4; t++) {
#pragma unroll
            for (int i = 0; i < 2; i++) {
                int r = lr0 + i * 64;
                const void* src = srcs[t] + (size_t)(rows[t] + r) * D_MODEL + k0 + lc0 * 8;
                uint32_t dst = sb + offs[t] + swz64((uint32_t)(r * 64 + lc0 * 16));
                CP_ASYNC16(dst, src);
            }
        }
    };

    load_stage(0, 0);
    CP_COMMIT();

    for (int it = 0; it < GK_ITERS2; it++) {
        const int cur = it & 1;
        CP_WAIT0();
        __syncthreads();
        if (it + 1 < GK_ITERS2) { load_stage(it + 1, cur ^ 1); CP_COMMIT(); }

        const uint32_t sb = sbase + cur * STAGE_B;
#pragma unroll
        for (int ks = 0; ks < 2; ks++) {
            const uint32_t kbyte = (uint32_t)(ks * 32);

            uint32_t bh[8], bl[8];
            LDSM_X4(bh[0], bh[1], bh[2], bh[3], sb + TO_BHI + swz64(b_rowpart + kbyte));
            LDSM_X4(bh[4], bh[5], bh[6], bh[7], sb + TO_BHI + swz64(b_rowpart + 1024 + kbyte));
            LDSM_X4(bl[0], bl[1], bl[2], bl[3], sb + TO_BLO + swz64(b_rowpart + kbyte));
            LDSM_X4(bl[4], bl[5], bl[6], bl[7], sb + TO_BLO + swz64(b_rowpart + 1024 + kbyte));

            uint32_t af[16];
#pragma unroll
            for (int mt = 0; mt < 4; mt++) {
                uint32_t ad = sb + TO_AHI + swz64(a_rowpart + (uint32_t)(mt * 1024) + kbyte);
                LDSM_X4(af[mt * 4 + 0], af[mt * 4 + 1], af[mt * 4 + 2], af[mt * 4 + 3], ad);
            }
#pragma unroll
            for (int mt = 0; mt < 4; mt++)
#pragma unroll
                for (int nt = 0; nt < 4; nt++)
                    mma_bf16(acc[mt][nt][0], acc[mt][nt][1], acc[mt][nt][2], acc[mt][nt][3],
                             af[mt*4+0], af[mt*4+1], af[mt*4+2], af[mt*4+3],
                             bh[nt*2+0], bh[nt*2+1]);
#pragma unroll
            for (int mt = 0; mt < 4; mt++)
#pragma unroll
                for (int nt = 0; nt < 4; nt++)
                    mma_bf16(acc[mt][nt][0], acc[mt][nt][1], acc[mt][nt][2], acc[mt][nt][3],
                             af[mt*4+0], af[mt*4+1], af[mt*4+2], af[mt*4+3],
                             bl[nt*2+0], bl[nt*2+1]);
#pragma unroll
            for (int mt = 0; mt < 4; mt++) {
                uint32_t ad = sb + TO_ALO + swz64(a_rowpart + (uint32_t)(mt * 1024) + kbyte);
                LDSM_X4(af[mt * 4 + 0], af[mt * 4 + 1], af[mt * 4 + 2], af[mt * 4 + 3], ad);
            }
#pragma unroll
            for (int mt = 0; mt < 4; mt++)
#pragma unroll
                for (int nt = 0; nt < 4; nt++)
                    mma_bf16(acc[mt][nt][0], acc[mt][nt][1], acc[mt][nt][2], acc[mt][nt][3],
                             af[mt*4+0], af[mt*4+1], af[mt*4+2], af[mt*4+3],
                             bh[nt*2+0], bh[nt*2+1]);
        }
        __syncthreads();
    }

#pragma unroll
    for (int mt = 0; mt < 4; mt++) {
        int row = m0 + warp_m * 64 + mt * 16 + (lane >> 2);
#pragma unroll
        for (int nt = 0; nt < 4; nt++) {
            int col = n0 + warp_n * 32 + nt * 8 + (lane & 3) * 2;
            if (BF16OUT) {
                uint32_t h01, l01, h23, l23;
                pack_hilo(acc[mt][nt][0], acc[mt][nt][1], h01, l01);
                pack_hilo(acc[mt][nt][2], acc[mt][nt][3], h23, l23);
                *(uint32_t*)(Chi + (size_t)row * D_MODEL + col)       = h01;
                *(uint32_t*)(Clo + (size_t)row * D_MODEL + col)       = l01;
                *(uint32_t*)(Chi + (size_t)(row + 8) * D_MODEL + col) = h23;
                *(uint32_t*)(Clo + (size_t)(row + 8) * D_MODEL + col) = l23;
            } else {
                *(float2*)(C0 + (size_t)row * D_MODEL + col) =
                    make_float2(acc[mt][nt][0], acc[mt][nt][1]);
                *(float2*)(C0 + (size_t)(row + 8) * D_MODEL + col) =
                    make_float2(acc[mt][nt][2], acc[mt][nt][3]);
            }
        }
    }
}

// ---------------------------------------------------------------------------
// Flash attention, bf16x3, causal. BQ=64, BKV=32, 4 warps, 2 CTAs/SM.
// Unnormalized softmax (R9 champion); Q_hi AND Q_lo fragments hoisted to regs.
// ---------------------------------------------------------------------------
#define ATT_QHI  0
#define ATT_QLO  16384
#define ATT_KV0  32768
#define KV_STAGE 32768
#define KVO_KHI  0
#define KVO_KLO  8192
#define KVO_VHI  16384
#define KVO_VLO  24576
#define ATT_SMEM (ATT_KV0 + 2 * KV_STAGE)   // 98304

__global__ __launch_bounds__(128, 2) void attn_mma_kernel(const int* __restrict__ causal_flag)
{
    extern __shared__ char smem[];
    const uint32_t sb = smem_u32(smem);
    const int tid  = threadIdx.x;
    const int w    = tid >> 5;
    const int lane = tid & 31;
    const int q0   = (gridDim.x - 1 - blockIdx.x) * 64;
    const int h    = blockIdx.y;
    const int causal = *causal_flag;
    const float sc2 = 0.08838834764831845f * 1.4426950408889634f;  // sm_scale*log2e

#pragma unroll
    for (int t = 0; t < 2; t++) {
        const __nv_bfloat16* src = t ? g_qlo : g_qhi;
        const uint32_t dst = t ? ATT_QLO : ATT_QHI;
#pragma unroll
        for (int i = 0; i < 8; i++) {
            int f = i * 128 + tid;
            int row = f >> 4, ch = f & 15;
            uint4 v = *(const uint4*)(src + (size_t)(q0 + row) * D_MODEL + h * HDIM + ch * 8);
            *(uint4*)(smem + dst + vswz((uint32_t)(row * 256 + ch * 16))) = v;
        }
    }

    const int kr0 = tid >> 4;
    const int kc0 = tid & 15;

    auto load_kv = [&](int kb, int stage) {
        const int k0 = kb * 32;
        const uint32_t base = ATT_KV0 + stage * KV_STAGE;
        const __nv_bfloat16* srcs[4] = { g_khi, g_klo, g_vhi, g_vlo };
        const uint32_t offs[4] = { KVO_KHI, KVO_KLO, KVO_VHI, KVO_VLO };
#pragma unroll
        for (int t = 0; t < 4; t++) {
#pragma unroll
            for (int i = 0; i < 4; i++) {
                int row = kr0 + i * 8;
                const void* src = srcs[t] + (size_t)(k0 + row) * D_MODEL + h * HDIM + kc0 * 8;
                uint32_t dst = sb + base + offs[t] + vswz((uint32_t)(row * 256 + kc0 * 16));
                CP_ASYNC16(dst, src);
            }
        }
    };

    load_kv(0, 0);
    CP_COMMIT();

    const int rq  = lane >> 2;
    const int cb  = (lane & 3) * 2;
    const int rg0 = q0 + w * 16 + rq;
    const int rg1 = rg0 + 8;

    const uint32_t a_row = (uint32_t)(w * 16 + (lane & 15));
    const uint32_t a_xr  = (a_row & 7) << 4;
    const uint32_t a_cb  = ((lane >> 4) & 1) * 16;
    const uint32_t k_rbase = ((lane >> 4) & 1) * 8 + (lane & 7);
    const uint32_t k_cb    = ((lane >> 3) & 1) * 16;
    const uint32_t v_rbase = ((lane >> 3) & 1) * 8 + (lane & 7);
    const uint32_t v_cb    = ((lane >> 4) & 1) * 16;

    // ---- hoist Q hi AND lo fragments into registers (loop-invariant) ----
    __syncthreads();
    uint32_t qh[8][4], ql[8][4];
#pragma unroll
    for (int ks = 0; ks < 8; ks++) {
        const uint32_t aoff = a_row * 256 + (((uint32_t)(ks * 32) + a_cb) ^ a_xr);
        LDSM_X4(qh[ks][0], qh[ks][1], qh[ks][2], qh[ks][3], sb + ATT_QHI + aoff);
        LDSM_X4(ql[ks][0], ql[ks][1], ql[ks][2], ql[ks][3], sb + ATT_QLO + aoff);
    }

    float o[16][4];
#pragma unroll
    for (int i = 0; i < 16; i++)
#pragma unroll
        for (int t = 0; t < 4; t++) o[i][t] = 0.0f;
    float l0 = 0.0f, l1 = 0.0f;

    const int kb_max = causal ? (q0 + 63) / 32 : (S_LEN / 32 - 1);

    for (int kb = 0; kb <= kb_max; kb++) {
        const int k0 = kb * 32;
        const int cur = kb & 1;
        CP_WAIT0();
        __syncthreads();
        if (kb + 1 <= kb_max) { load_kv(kb + 1, cur ^ 1); CP_COMMIT(); }

        const uint32_t kvb = ATT_KV0 + cur * KV_STAGE;

        float s[4][4];
#pragma unroll
        for (int i = 0; i < 4; i++)
#pragma unroll
            for (int t = 0; t < 4; t++) s[i][t] = 0.0f;

#pragma unroll
        for (int ks = 0; ks < 8; ks++) {
            uint32_t bh[8], bl[8];
#pragma unroll
            for (int ng = 0; ng < 2; ng++) {
                const uint32_t krow = (uint32_t)(ng * 16) + k_rbase;
                const uint32_t koff = krow * 256 + (((uint32_t)(ks * 32) + k_cb) ^ ((krow & 7) << 4));
                LDSM_X4(bh[4*ng+0], bh[4*ng+1], bh[4*ng+2], bh[4*ng+3], sb + kvb + KVO_KHI + koff);
                LDSM_X4(bl[4*ng+0], bl[4*ng+1], bl[4*ng+2], bl[4*ng+3], sb + kvb + KVO_KLO + koff);
            }
#pragma unroll
            for (int ng = 0; ng < 2; ng++) {
                mma_bf16(s[2*ng][0], s[2*ng][1], s[2*ng][2], s[2*ng][3],
                         qh[ks][0], qh[ks][1], qh[ks][2], qh[ks][3], bh[4*ng+0], bh[4*ng+1]);
                mma_bf16(s[2*ng+1][0], s[2*ng+1][1], s[2*ng+1][2], s[2*ng+1][3],
                         qh[ks][0], qh[ks][1], qh[ks][2], qh[ks][3], bh[4*ng+2], bh[4*ng+3]);
            }
#pragma unroll
            for (int ng = 0; ng < 2; ng++) {
                mma_bf16(s[2*ng][0], s[2*ng][1], s[2*ng][2], s[2*ng][3],
                         qh[ks][0], qh[ks][1], qh[ks][2], qh[ks][3], bl[4*ng+0], bl[4*ng+1]);
                mma_bf16(s[2*ng+1][0], s[2*ng+1][1], s[2*ng+1][2], s[2*ng+1][3],
                         qh[ks][0], qh[ks][1], qh[ks][2], qh[ks][3], bl[4*ng+2], bl[4*ng+3]);
            }
#pragma unroll
            for (int ng = 0; ng < 2; ng++) {
                mma_bf16(s[2*ng][0], s[2*ng][1], s[2*ng][2], s[2*ng][3],
                         ql[ks][0], ql[ks][1], ql[ks][2], ql[ks][3], bh[4*ng+0], bh[4*ng+1]);
                mma_bf16(s[2*ng+1][0], s[2*ng+1][1], s[2*ng+1][2], s[2*ng+1][3],
                         ql[ks][0], ql[ks][1], ql[ks][2], ql[ks][3], bh[4*ng+2], bh[4*ng+3]);
            }
        }

        const bool do_mask = (causal != 0) && (k0 + 31 > q0);
#pragma unroll
        for (int nt = 0; nt < 4; nt++) {
            const int cg = k0 + nt * 8 + cb;
            float p0 = fast_exp2(s[nt][0] * sc2);
            float p1 = fast_exp2(s[nt][1] * sc2);
            float p2 = fast_exp2(s[nt][2] * sc2);
            float p3 = fast_exp2(s[nt][3] * sc2);
            if (do_mask) {
                if (cg     > rg0) p0 = 0.0f;
                if (cg + 1 > rg0) p1 = 0.0f;
                if (cg     > rg1) p2 = 0.0f;
                if (cg + 1 > rg1) p3 = 0.0f;
            }
            s[nt][0] = p0; s[nt][1] = p1; s[nt][2] = p2; s[nt][3] = p3;
            l0 += p0 + p1;
            l1 += p2 + p3;
        }

        uint32_t ph[2][4], pl[2][4];
#pragma unroll
        for (int ks = 0; ks < 2; ks++) {
            pack_hilo(s[2*ks][0],   s[2*ks][1],   ph[ks][0], pl[ks][0]);
            pack_hilo(s[2*ks][2],   s[2*ks][3],   ph[ks][1], pl[ks][1]);
            pack_hilo(s[2*ks+1][0], s[2*ks+1][1], ph[ks][2], pl[ks][2]);
            pack_hilo(s[2*ks+1][2], s[2*ks+1][3], ph[ks][3], pl[ks][3]);
        }

#pragma unroll
        for (int ks = 0; ks < 2; ks++) {
            const uint32_t vrow = (uint32_t)(ks * 16) + v_rbase;
            const uint32_t vxr  = (vrow & 7) << 4;
#pragma unroll
            for (int np = 0; np < 4; np++) {
                const int g0 = 2 * np, g1 = 2 * np + 1;
                const uint32_t voffA = vrow * 256 + (((uint32_t)(g0 * 32) + v_cb) ^ vxr);
                const uint32_t voffB = vrow * 256 + (((uint32_t)(g1 * 32) + v_cb) ^ vxr);
                uint32_t va[4], vb[4], wa[4], wb[4];
                LDSM_X4_T(va[0], va[1], va[2], va[3], sb + kvb + KVO_VHI + voffA);
                LDSM_X4_T(vb[0], vb[1], vb[2], vb[3], sb + kvb + KVO_VHI + voffB);
                LDSM_X4_T(wa[0], wa[1], wa[2], wa[3], sb + kvb + KVO_VLO + voffA);
                LDSM_X4_T(wb[0], wb[1], wb[2], wb[3], sb + kvb + KVO_VLO + voffB);
                mma_bf16(o[2*g0][0], o[2*g0][1], o[2*g0][2], o[2*g0][3],
                         ph[ks][0], ph[ks][1], ph[ks][2], ph[ks][3], va[0], va[1]);
                mma_bf16(o[2*g0+1][0], o[2*g0+1][1], o[2*g0+1][2], o[2*g0+1][3],
                         ph[ks][0], ph[ks][1], ph[ks][2], ph[ks][3], va[2], va[3]);
                mma_bf16(o[2*g1][0], o[2*g1][1], o[2*g1][2], o[2*g1][3],
                         ph[ks][0], ph[ks][1], ph[ks][2], ph[ks][3], vb[0], vb[1]);
                mma_bf16(o[2*g1+1][0], o[2*g1+1][1], o[2*g1+1][2], o[2*g1+1][3],
                         ph[ks][0], ph[ks][1], ph[ks][2], ph[ks][3], vb[2], vb[3]);
                mma_bf16(o[2*g0][0], o[2*g0][1], o[2*g0][2], o[2*g0][3],
                         ph[ks][0], ph[ks][1], ph[ks][2], ph[ks][3], wa[0], wa[1]);
                mma_bf16(o[2*g0+1][0], o[2*g0+1][1], o[2*g0+1][2], o[2*g0+1][3],
                         ph[ks][0], ph[ks][1], ph[ks][2], ph[ks][3], wa[2], wa[3]);
                mma_bf16(o[2*g1][0], o[2*g1][1], o[2*g1][2], o[2*g1][3],
                         ph[ks][0], ph[ks][1], ph[ks][2], ph[ks][3], wb[0], wb[1]);
                mma_bf16(o[2*g1+1][0], o[2*g1+1][1], o[2*g1+1][2], o[2*g1+1][3],
                         ph[ks][0], ph[ks][1], ph[ks][2], ph[ks][3], wb[2], wb[3]);
                mma_bf16(o[2*g0][0], o[2*g0][1], o[2*g0][2], o[2*g0][3],
                         pl[ks][0], pl[ks][1], pl[ks][2], pl[ks][3], va[0], va[1]);
                mma_bf16(o[2*g0+1][0], o[2*g0+1][1], o[2*g0+1][2], o[2*g0+1][3],
                         pl[ks][0], pl[ks][1], pl[ks][2], pl[ks][3], va[2], va[3]);
                mma_bf16(o[2*g1][0], o[2*g1][1], o[2*g1][2], o[2*g1][3],
                         pl[ks][0], pl[ks][1], pl[ks][2], pl[ks][3], vb[0], vb[1]);
                mma_bf16(o[2*g1+1][0], o[2*g1+1][1], o[2*g1+1][2], o[2*g1+1][3],
                         pl[ks][0], pl[ks][1], pl[ks][2], pl[ks][3], vb[2], vb[3]);
            }
        }
    }

    // ---- epilogue ----
    l0 += __shfl_xor_sync(0xffffffffu, l0, 1);
    l0 += __shfl_xor_sync(0xffffffffu, l0, 2);
    l1 += __shfl_xor_sync(0xffffffffu, l1, 1);
    l1 += __shfl_xor_sync(0xffffffffu, l1, 2);
    const float inv0 = 1.0f / l0, inv1 = 1.0f / l1;
#pragma unroll
    for (int nt = 0; nt < 16; nt++) {
        const int col = h * HDIM + nt * 8 + cb;
        uint32_t hA, lA, hB, lB;
        pack_hilo(o[nt][0] * inv0, o[nt][1] * inv0, hA, lA);
        pack_hilo(o[nt][2] * inv1, o[nt][3] * inv1, hB, lB);
        *(uint32_t*)(g_ohi + (size_t)rg0 * D_MODEL + col) = hA;
        *(uint32_t*)(g_olo + (size_t)rg0 * D_MODEL + col) = lA;
        *(uint32_t*)(g_ohi + (size_t)rg1 * D_MODEL + col) = hB;
        *(uint32_t*)(g_olo + (size_t)rg1 * D_MODEL + col) = lB;
    }
}

// ---------------------------------------------------------------------------
// Launch
// ---------------------------------------------------------------------------
extern "C" void kernel_launch(void* const* d_in, const int* in_sizes, int n_in,
                              void* d_out, int out_size)
{
    const float* x  = (const float*)d_in[0];
    const float* wq = (const float*)d_in[1];
    const float* wk = (const float*)d_in[2];
    const float* wv = (const float*)d_in[3];
    const float* wo = (const float*)d_in[4];
    const int* causal = (const int*)d_in[5];
    float* out = (float*)d_out;

    __nv_bfloat16 *xhi, *xlo, *ohi, *olo;
    __nv_bfloat16 *qhi, *qlo, *khi, *klo, *vhi, *vlo;
    __nv_bfloat16 *wqh, *wql, *wkh, *wkl, *wvh, *wvl, *woh, *wol;
    cudaGetSymbolAddress((void**)&xhi, g_xhi);  cudaGetSymbolAddress((void**)&xlo, g_xlo);
    cudaGetSymbolAddress((void**)&ohi, g_ohi);  cudaGetSymbolAddress((void**)&olo, g_olo);
    cudaGetSymbolAddress((void**)&qhi, g_qhi);  cudaGetSymbolAddress((void**)&qlo, g_qlo);
    cudaGetSymbolAddress((void**)&khi, g_khi);  cudaGetSymbolAddress((void**)&klo, g_klo);
    cudaGetSymbolAddress((void**)&vhi, g_vhi);  cudaGetSymbolAddress((void**)&vlo, g_vlo);
    cudaGetSymbolAddress((void**)&wqh, g_wqhi); cudaGetSymbolAddress((void**)&wql, g_wqlo);
    cudaGetSymbolAddress((void**)&wkh, g_wkhi); cudaGetSymbolAddress((void**)&wkl, g_wklo);
    cudaGetSymbolAddress((void**)&wvh, g_wvhi); cudaGetSymbolAddress((void**)&wvl, g_wvlo);
    cudaGetSymbolAddress((void**)&woh, g_wohi); cudaGetSymbolAddress((void**)&wol, g_wolo);

    const int nx4 = S_LEN * D_MODEL / 4;
    const int nw4 = D_MODEL * D_MODEL / 4;

    split_all_kernel<<<dim3(nx4 / 256, 5), 256>>>(
        (const float4*)x,
        (const float4*)wq, (const float4*)wk, (const float4*)wv, (const float4*)wo,
        (__nv_bfloat162*)xhi, (__nv_bfloat162*)xlo,
        (__nv_bfloat162*)wqh, (__nv_bfloat162*)wql,
        (__nv_bfloat162*)wkh, (__nv_bfloat162*)wkl,
        (__nv_bfloat162*)wvh, (__nv_bfloat162*)wvl,
        (__nv_bfloat162*)woh, (__nv_bfloat162*)wol, nw4, nx4);

    cudaFuncSetAttribute(gemm_mma_kernel<true>,  cudaFuncAttributeMaxDynamicSharedMemorySize, GEMM_SMEM);
    cudaFuncSetAttribute(gemm_mma_kernel<false>, cudaFuncAttributeMaxDynamicSharedMemorySize, GEMM_SMEM);
    dim3 gqkv(D_MODEL / 128, S_LEN / 128, 3);
    gemm_mma_kernel<true><<<gqkv, 256, GEMM_SMEM>>>(
        xhi, xlo, wqh, wql, wkh, wkl, wvh, wvl,
        nullptr, qhi, qlo, khi, klo, vhi, vlo);

    cudaFuncSetAttribute(attn_mma_kernel, cudaFuncAttributeMaxDynamicSharedMemorySize, ATT_SMEM);
    attn_mma_kernel<<<dim3(S_LEN / 64, NHEADS), 128, ATT_SMEM>>>(causal);

    dim3 gout(D_MODEL / 128, S_LEN / 128, 1);
    gemm_mma_kernel<false><<<gout, 256, GEMM_SMEM>>>(
        ohi, olo, woh, wol, woh, wol, woh, wol,
        out, nullptr, nullptr, nullptr, nullptr, nullptr, nullptr);
}

// round 16
// speedup vs baseline: 1.0200x; 1.0200x over previous
#include <cuda_runtime.h>
#include <cuda_bf16.h>
#include <math.h>
#include <stdint.h>

#define S_LEN   4096
#define D_MODEL 2048
#define NHEADS  16
#define HDIM    128

// ---------------------------------------------------------------------------
// Scratch (device globals: allocation-guard-safe)
// ---------------------------------------------------------------------------
__device__ __nv_bfloat16 g_xhi[S_LEN * D_MODEL];
__device__ __nv_bfloat16 g_xlo[S_LEN * D_MODEL];
__device__ __nv_bfloat16 g_qhi[S_LEN * D_MODEL];
__device__ __nv_bfloat16 g_qlo[S_LEN * D_MODEL];
__device__ __nv_bfloat16 g_khi[S_LEN * D_MODEL];
__device__ __nv_bfloat16 g_klo[S_LEN * D_MODEL];
__device__ __nv_bfloat16 g_vhi[S_LEN * D_MODEL];
__device__ __nv_bfloat16 g_vlo[S_LEN * D_MODEL];
__device__ __nv_bfloat16 g_ohi[S_LEN * D_MODEL];
__device__ __nv_bfloat16 g_olo[S_LEN * D_MODEL];
__device__ __nv_bfloat16 g_wqhi[D_MODEL * D_MODEL];
__device__ __nv_bfloat16 g_wqlo[D_MODEL * D_MODEL];
__device__ __nv_bfloat16 g_wkhi[D_MODEL * D_MODEL];
__device__ __nv_bfloat16 g_wklo[D_MODEL * D_MODEL];
__device__ __nv_bfloat16 g_wvhi[D_MODEL * D_MODEL];
__device__ __nv_bfloat16 g_wvlo[D_MODEL * D_MODEL];
__device__ __nv_bfloat16 g_wohi[D_MODEL * D_MODEL];
__device__ __nv_bfloat16 g_wolo[D_MODEL * D_MODEL];

// ---------------------------------------------------------------------------
// Helpers
// ---------------------------------------------------------------------------
__device__ __forceinline__ uint32_t smem_u32(const void* p) {
    uint32_t a;
    asm("{ .reg .u64 t; cvta.to.shared.u64 t, %1; cvt.u32.u64 %0, t; }" : "=r"(a) : "l"(p));
    return a;
}

#define LDSM_X4(r0, r1, r2, r3, addr)                                         \
    asm volatile("ldmatrix.sync.aligned.m8n8.x4.shared.b16 {%0,%1,%2,%3}, [%4];" \
        : "=r"(r0), "=r"(r1), "=r"(r2), "=r"(r3) : "r"(addr))

#define LDSM_X4_T(r0, r1, r2, r3, addr)                                       \
    asm volatile("ldmatrix.sync.aligned.m8n8.x4.trans.shared.b16 {%0,%1,%2,%3}, [%4];" \
        : "=r"(r0), "=r"(r1), "=r"(r2), "=r"(r3) : "r"(addr))

#define CP_ASYNC16(dst, src)                                                  \
    asm volatile("cp.async.cg.shared.global [%0], [%1], 16;" :: "r"(dst), "l"(src))
#define CP_COMMIT() asm volatile("cp.async.commit_group;" ::: "memory")
#define CP_WAIT0()  asm volatile("cp.async.wait_group 0;" ::: "memory")

__device__ __forceinline__ void mma_bf16(float& c0, float& c1, float& c2, float& c3,
                                         uint32_t a0, uint32_t a1, uint32_t a2, uint32_t a3,
                                         uint32_t b0, uint32_t b1) {
    asm volatile(
        "mma.sync.aligned.m16n8k16.row.col.f32.bf16.bf16.f32 "
        "{%0,%1,%2,%3}, {%4,%5,%6,%7}, {%8,%9}, {%0,%1,%2,%3};"
        : "+f"(c0), "+f"(c1), "+f"(c2), "+f"(c3)
        : "r"(a0), "r"(a1), "r"(a2), "r"(a3), "r"(b0), "r"(b1));
}

__device__ __forceinline__ uint32_t pack2(__nv_bfloat16 a, __nv_bfloat16 b) {
    __nv_bfloat162 t(a, b);
    return *reinterpret_cast<uint32_t*>(&t);
}

__device__ __forceinline__ void pack_hilo(float x, float y, uint32_t& hi, uint32_t& lo) {
    __nv_bfloat16 hx = __float2bfloat16(x), hy = __float2bfloat16(y);
    float rx = x - __bfloat162float(hx), ry = y - __bfloat162float(hy);
    hi = pack2(hx, hy);
    lo = pack2(__float2bfloat16(rx), __float2bfloat16(ry));
}

__device__ __forceinline__ float fast_exp2(float x) {
    float r;
    asm("ex2.approx.ftz.f32 %0, %1;" : "=f"(r) : "f"(x));
    return r;
}

__device__ __forceinline__ uint32_t swz64(uint32_t off) { return off ^ ((off >> 3) & 0x30); }
__device__ __forceinline__ uint32_t vswz(uint32_t off)  { return off ^ ((off >> 4) & 0x70); }

// ---------------------------------------------------------------------------
// fp32 -> bf16 hi/lo splits
// ---------------------------------------------------------------------------
__global__ __launch_bounds__(256) void split_kernel(
    const float4* __restrict__ src, __nv_bfloat162* __restrict__ hi,
    __nv_bfloat162* __restrict__ lo, int n4)
{
    int i = blockIdx.x * blockDim.x + threadIdx.x;
    if (i >= n4) return;
    float4 v = src[i];
    uint32_t h0, l0, h1, l1;
    pack_hilo(v.x, v.y, h0, l0);
    pack_hilo(v.z, v.w, h1, l1);
    *reinterpret_cast<uint32_t*>(&hi[2 * i + 0]) = h0;
    *reinterpret_cast<uint32_t*>(&hi[2 * i + 1]) = h1;
    *reinterpret_cast<uint32_t*>(&lo[2 * i + 0]) = l0;
    *reinterpret_cast<uint32_t*>(&lo[2 * i + 1]) = l1;
}

__global__ __launch_bounds__(256) void split_w_kernel(
    const float4* __restrict__ w0, const float4* __restrict__ w1,
    const float4* __restrict__ w2, const float4* __restrict__ w3,
    __nv_bfloat162* __restrict__ h0p, __nv_bfloat162* __restrict__ l0p,
    __nv_bfloat162* __restrict__ h1p, __nv_bfloat162* __restrict__ l1p,
    __nv_bfloat162* __restrict__ h2p, __nv_bfloat162* __restrict__ l2p,
    __nv_bfloat162* __restrict__ h3p, __nv_bfloat162* __restrict__ l3p,
    int n4)
{
    int i = blockIdx.x * blockDim.x + threadIdx.x;
    if (i >= n4) return;
    const int s = blockIdx.y;
    const float4* src = (s == 0) ? w0 : (s == 1) ? w1 : (s == 2) ? w2 : w3;
    __nv_bfloat162* hi = (s == 0) ? h0p : (s == 1) ? h1p : (s == 2) ? h2p : h3p;
    __nv_bfloat162* lo = (s == 0) ? l0p : (s == 1) ? l1p : (s == 2) ? l2p : l3p;
    float4 v = src[i];
    uint32_t a0, b0, a1, b1;
    pack_hilo(v.x, v.y, a0, b0);
    pack_hilo(v.z, v.w, a1, b1);
    *reinterpret_cast<uint32_t*>(&hi[2 * i + 0]) = a0;
    *reinterpret_cast<uint32_t*>(&hi[2 * i + 1]) = a1;
    *reinterpret_cast<uint32_t*>(&lo[2 * i + 0]) = b0;
    *reinterpret_cast<uint32_t*>(&lo[2 * i + 1]) = b1;
}

// ---------------------------------------------------------------------------
// bf16x3 GEMM, cp.async 2-stage (Round-9 champion config).
// ---------------------------------------------------------------------------
#define GBK2      32
#define GK_ITERS2 (D_MODEL / GBK2)
#define STAGE_B   32768
#define TO_AHI    0
#define TO_ALO    8192
#define TO_BHI    16384
#define TO_BLO    24576
#define GEMM_SMEM (2 * STAGE_B)   // 65536

template<bool BF16OUT>
__global__ __launch_bounds__(256) void gemm_mma_kernel(
    const __nv_bfloat16* __restrict__ Ahi, const __nv_bfloat16* __restrict__ Alo,
    const __nv_bfloat16* __restrict__ Bhi0, const __nv_bfloat16* __restrict__ Blo0,
    const __nv_bfloat16* __restrict__ Bhi1, const __nv_bfloat16* __restrict__ Blo1,
    const __nv_bfloat16* __restrict__ Bhi2, const __nv_bfloat16* __restrict__ Blo2,
    float* __restrict__ C0,
    __nv_bfloat16* __restrict__ Chi0, __nv_bfloat16* __restrict__ Clo0,
    __nv_bfloat16* __restrict__ Chi1, __nv_bfloat16* __restrict__ Clo1,
    __nv_bfloat16* __restrict__ Chi2, __nv_bfloat16* __restrict__ Clo2)
{
    extern __shared__ char smem[];
    const uint32_t sbase = smem_u32(smem);
    const int tid  = threadIdx.x;
    const int wid  = tid >> 5;
    const int lane = tid & 31;

    const __nv_bfloat16* Bhi = (blockIdx.z == 0) ? Bhi0 : (blockIdx.z == 1) ? Bhi1 : Bhi2;
    const __nv_bfloat16* Blo = (blockIdx.z == 0) ? Blo0 : (blockIdx.z == 1) ? Blo1 : Blo2;
    __nv_bfloat16* Chi = (blockIdx.z == 0) ? Chi0 : (blockIdx.z == 1) ? Chi1 : Chi2;
    __nv_bfloat16* Clo = (blockIdx.z == 0) ? Clo0 : (blockIdx.z == 1) ? Clo1 : Clo2;

    const int m0 = blockIdx.y * 128;
    const int n0 = blockIdx.x * 128;

    const int warp_m = wid & 1;
    const int warp_n = wid >> 1;

    const int lr0 = tid >> 2;
    const int lc0 = tid & 3;

    const uint32_t a_rowpart = (uint32_t)((warp_m * 64 + (lane & 15)) * 64 + (lane >> 4) * 16);
    const uint32_t b_rowpart = (uint32_t)((warp_n * 32 + (lane & 7) + ((lane >> 4) << 3)) * 64
                                          + ((lane >> 3) & 1) * 16);

    float acc[4][4][4];
#pragma unroll
    for (int i = 0; i < 4; i++)
#pragma unroll
        for (int j = 0; j < 4; j++)
#pragma unroll
            for (int t = 0; t < 4; t++) acc[i][j][t] = 0.0f;

    auto load_stage = [&](int it, int stage) {
        const int k0 = it * GBK2;
        const uint32_t sb = sbase + stage * STAGE_B;
        const __nv_bfloat16* srcs[4] = { Ahi, Alo, Bhi, Blo };
        const uint32_t offs[4] = { TO_AHI, TO_ALO, TO_BHI, TO_BLO };
        const int rows[4] = { m0, m0, n0, n0 };
#pragma unroll
        for (int t = 0; t < 4; t++) {
#pragma unroll
            for (int i = 0; i < 2; i++) {
                int r = lr0 + i * 64;
                const void* src = srcs[t] + (size_t)(rows[t] + r) * D_MODEL + k0 + lc0 * 8;
                uint32_t dst = sb + offs[t] + swz64((uint32_t)(r * 64 + lc0 * 16));
                CP_ASYNC16(dst, src);
            }
        }
    };

    load_stage(0, 0);
    CP_COMMIT();

    for (int it = 0; it < GK_ITERS2; it++) {
        const int cur = it & 1;
        CP_WAIT0();
        __syncthreads();
        if (it + 1 < GK_ITERS2) { load_stage(it + 1, cur ^ 1); CP_COMMIT(); }

        const uint32_t sb = sbase + cur * STAGE_B;
#pragma unroll
        for (int ks = 0; ks < 2; ks++) {
            const uint32_t kbyte = (uint32_t)(ks * 32);

            uint32_t bh[8], bl[8];
            LDSM_X4(bh[0], bh[1], bh[2], bh[3], sb + TO_BHI + swz64(b_rowpart + kbyte));
            LDSM_X4(bh[4], bh[5], bh[6], bh[7], sb + TO_BHI + swz64(b_rowpart + 1024 + kbyte));
            LDSM_X4(bl[0], bl[1], bl[2], bl[3], sb + TO_BLO + swz64(b_rowpart + kbyte));
            LDSM_X4(bl[4], bl[5], bl[6], bl[7], sb + TO_BLO + swz64(b_rowpart + 1024 + kbyte));

            uint32_t af[16];
#pragma unroll
            for (int mt = 0; mt < 4; mt++) {
                uint32_t ad = sb + TO_AHI + swz64(a_rowpart + (uint32_t)(mt * 1024) + kbyte);
                LDSM_X4(af[mt * 4 + 0], af[mt * 4 + 1], af[mt * 4 + 2], af[mt * 4 + 3], ad);
            }
#pragma unroll
            for (int mt = 0; mt < 4; mt++)
#pragma unroll
                for (int nt = 0; nt < 4; nt++)
                    mma_bf16(acc[mt][nt][0], acc[mt][nt][1], acc[mt][nt][2], acc[mt][nt][3],
                             af[mt*4+0], af[mt*4+1], af[mt*4+2], af[mt*4+3],
                             bh[nt*2+0], bh[nt*2+1]);
#pragma unroll
            for (int mt = 0; mt < 4; mt++)
#pragma unroll
                for (int nt = 0; nt < 4; nt++)
                    mma_bf16(acc[mt][nt][0], acc[mt][nt][1], acc[mt][nt][2], acc[mt][nt][3],
                             af[mt*4+0], af[mt*4+1], af[mt*4+2], af[mt*4+3],
                             bl[nt*2+0], bl[nt*2+1]);
#pragma unroll
            for (int mt = 0; mt < 4; mt++) {
                uint32_t ad = sb + TO_ALO + swz64(a_rowpart + (uint32_t)(mt * 1024) + kbyte);
                LDSM_X4(af[mt * 4 + 0], af[mt * 4 + 1], af[mt * 4 + 2], af[mt * 4 + 3], ad);
            }
#pragma unroll
            for (int mt = 0; mt < 4; mt++)
#pragma unroll
                for (int nt = 0; nt < 4; nt++)
                    mma_bf16(acc[mt][nt][0], acc[mt][nt][1], acc[mt][nt][2], acc[mt][nt][3],
                             af[mt*4+0], af[mt*4+1], af[mt*4+2], af[mt*4+3],
                             bh[nt*2+0], bh[nt*2+1]);
        }
        __syncthreads();
    }

#pragma unroll
    for (int mt = 0; mt < 4; mt++) {
        int row = m0 + warp_m * 64 + mt * 16 + (lane >> 2);
#pragma unroll
        for (int nt = 0; nt < 4; nt++) {
            int col = n0 + warp_n * 32 + nt * 8 + (lane & 3) * 2;
            if (BF16OUT) {
                uint32_t h01, l01, h23, l23;
                pack_hilo(acc[mt][nt][0], acc[mt][nt][1], h01, l01);
                pack_hilo(acc[mt][nt][2], acc[mt][nt][3], h23, l23);
                *(uint32_t*)(Chi + (size_t)row * D_MODEL + col)       = h01;
                *(uint32_t*)(Clo + (size_t)row * D_MODEL + col)       = l01;
                *(uint32_t*)(Chi + (size_t)(row + 8) * D_MODEL + col) = h23;
                *(uint32_t*)(Clo + (size_t)(row + 8) * D_MODEL + col) = l23;
            } else {
                *(float2*)(C0 + (size_t)row * D_MODEL + col) =
                    make_float2(acc[mt][nt][0], acc[mt][nt][1]);
                *(float2*)(C0 + (size_t)(row + 8) * D_MODEL + col) =
                    make_float2(acc[mt][nt][2], acc[mt][nt][3]);
            }
        }
    }
}

// ---------------------------------------------------------------------------
// Flash attention, bf16x3, causal. BQ=64, BKV=32, 4 warps, 2 CTAs/SM.
// Unnormalized softmax; Q_hi fragments hoisted to registers (233 regs).
// ---------------------------------------------------------------------------
#define ATT_QHI  0
#define ATT_QLO  16384
#define ATT_KV0  32768
#define KV_STAGE 32768
#define KVO_KHI  0
#define KVO_KLO  8192
#define KVO_VHI  16384
#define KVO_VLO  24576
#define ATT_SMEM (ATT_KV0 + 2 * KV_STAGE)   // 98304

__global__ __launch_bounds__(128, 2) void attn_mma_kernel(const int* __restrict__ causal_flag)
{
    extern __shared__ char smem[];
    const uint32_t sb = smem_u32(smem);
    const int tid  = threadIdx.x;
    const int w    = tid >> 5;
    const int lane = tid & 31;
    const int q0   = (gridDim.x - 1 - blockIdx.x) * 64;
    const int h    = blockIdx.y;
    const int causal = *causal_flag;
    const float sc2 = 0.08838834764831845f * 1.4426950408889634f;  // sm_scale*log2e

    // ---- Q hi/lo -> smem ----
#pragma unroll
    for (int t = 0; t < 2; t++) {
        const __nv_bfloat16* src = t ? g_qlo : g_qhi;
        const uint32_t dst = t ? ATT_QLO : ATT_QHI;
#pragma unroll
        for (int i = 0; i < 8; i++) {
            int f = i * 128 + tid;
            int row = f >> 4, ch = f & 15;
            uint4 v = *(const uint4*)(src + (size_t)(q0 + row) * D_MODEL + h * HDIM + ch * 8);
            *(uint4*)(smem + dst + vswz((uint32_t)(row * 256 + ch * 16))) = v;
        }
    }

    const int kr0 = tid >> 4;
    const int kc0 = tid & 15;

    auto load_kv = [&](int kb, int stage) {
        const int k0 = kb * 32;
        const uint32_t base = ATT_KV0 + stage * KV_STAGE;
        const __nv_bfloat16* srcs[4] = { g_khi, g_klo, g_vhi, g_vlo };
        const uint32_t offs[4] = { KVO_KHI, KVO_KLO, KVO_VHI, KVO_VLO };
#pragma unroll
        for (int t = 0; t < 4; t++) {
#pragma unroll
            for (int i = 0; i < 4; i++) {
                int row = kr0 + i * 8;
                const void* src = srcs[t] + (size_t)(k0 + row) * D_MODEL + h * HDIM + kc0 * 8;
                uint32_t dst = sb + base + offs[t] + vswz((uint32_t)(row * 256 + kc0 * 16));
                CP_ASYNC16(dst, src);
            }
        }
    };

    // Issue first KV load before hoisting Q (overlap)
    load_kv(0, 0);
    CP_COMMIT();

    const int rq  = lane >> 2;
    const int cb  = (lane & 3) * 2;
    const int rg0 = q0 + w * 16 + rq;
    const int rg1 = rg0 + 8;

    const uint32_t a_row = (uint32_t)(w * 16 + (lane & 15));
    const uint32_t a_xr  = (a_row & 7) << 4;
    const uint32_t a_cb  = ((lane >> 4) & 1) * 16;
    const uint32_t k_rbase = ((lane >> 4) & 1) * 8 + (lane & 7);
    const uint32_t k_cb    = ((lane >> 3) & 1) * 16;
    const uint32_t v_rbase = ((lane >> 3) & 1) * 8 + (lane & 7);
    const uint32_t v_cb    = ((lane >> 4) & 1) * 16;

    // ---- hoist Q_hi fragments into registers (invariant over KV loop) ----
    __syncthreads();
    uint32_t qh[8][4];
#pragma unroll
    for (int ks = 0; ks < 8; ks++) {
        const uint32_t aoff = a_row * 256 + (((uint32_t)(ks * 32) + a_cb) ^ a_xr);
        LDSM_X4(qh[ks][0], qh[ks][1], qh[ks][2], qh[ks][3], sb + ATT_QHI + aoff);
    }

    float o[16][4];
#pragma unroll
    for (int i = 0; i < 16; i++)
#pragma unroll
        for (int t = 0; t < 4; t++) o[i][t] = 0.0f;
    float l0 = 0.0f, l1 = 0.0f;

    const int kb_max = causal ? (q0 + 63) / 32 : (S_LEN / 32 - 1);

    for (int kb = 0; kb <= kb_max; kb++) {
        const int k0 = kb * 32;
        const int cur = kb & 1;
        CP_WAIT0();
        __syncthreads();
        if (kb + 1 <= kb_max) { load_kv(kb + 1, cur ^ 1); CP_COMMIT(); }

        const uint32_t kvb = ATT_KV0 + cur * KV_STAGE;

        float s[4][4];
#pragma unroll
        for (int i = 0; i < 4; i++)
#pragma unroll
            for (int t = 0; t < 4; t++) s[i][t] = 0.0f;

#pragma unroll
        for (int ks = 0; ks < 8; ks++) {
            const uint32_t aoff = a_row * 256 + (((uint32_t)(ks * 32) + a_cb) ^ a_xr);
            uint32_t al0, al1, al2, al3;
            LDSM_X4(al0, al1, al2, al3, sb + ATT_QLO + aoff);

            uint32_t bh[8], bl[8];
#pragma unroll
            for (int ng = 0; ng < 2; ng++) {
                const uint32_t krow = (uint32_t)(ng * 16) + k_rbase;
                const uint32_t koff = krow * 256 + (((uint32_t)(ks * 32) + k_cb) ^ ((krow & 7) << 4));
                LDSM_X4(bh[4*ng+0], bh[4*ng+1], bh[4*ng+2], bh[4*ng+3], sb + kvb + KVO_KHI + koff);
                LDSM_X4(bl[4*ng+0], bl[4*ng+1], bl[4*ng+2], bl[4*ng+3], sb + kvb + KVO_KLO + koff);
            }
#pragma unroll
            for (int ng = 0; ng < 2; ng++) {
                mma_bf16(s[2*ng][0], s[2*ng][1], s[2*ng][2], s[2*ng][3],
                         qh[ks][0], qh[ks][1], qh[ks][2], qh[ks][3], bh[4*ng+0], bh[4*ng+1]);
                mma_bf16(s[2*ng+1][0], s[2*ng+1][1], s[2*ng+1][2], s[2*ng+1][3],
                         qh[ks][0], qh[ks][1], qh[ks][2], qh[ks][3], bh[4*ng+2], bh[4*ng+3]);
            }
#pragma unroll
            for (int ng = 0; ng < 2; ng++) {
                mma_bf16(s[2*ng][0], s[2*ng][1], s[2*ng][2], s[2*ng][3],
                         qh[ks][0], qh[ks][1], qh[ks][2], qh[ks][3], bl[4*ng+0], bl[4*ng+1]);
                mma_bf16(s[2*ng+1][0], s[2*ng+1][1], s[2*ng+1][2], s[2*ng+1][3],
                         qh[ks][0], qh[ks][1], qh[ks][2], qh[ks][3], bl[4*ng+2], bl[4*ng+3]);
            }
#pragma unroll
            for (int ng = 0; ng < 2; ng++) {
                mma_bf16(s[2*ng][0], s[2*ng][1], s[2*ng][2], s[2*ng][3],
                         al0, al1, al2, al3, bh[4*ng+0], bh[4*ng+1]);
                mma_bf16(s[2*ng+1][0], s[2*ng+1][1], s[2*ng+1][2], s[2*ng+1][3],
                         al0, al1, al2, al3, bh[4*ng+2], bh[4*ng+3]);
            }
        }

        const bool do_mask = (causal != 0) && (k0 + 31 > q0);
#pragma unroll
        for (int nt = 0; nt < 4; nt++) {
            const int cg = k0 + nt * 8 + cb;
            float p0 = fast_exp2(s[nt][0] * sc2);
            float p1 = fast_exp2(s[nt][1] * sc2);
            float p2 = fast_exp2(s[nt][2] * sc2);
            float p3 = fast_exp2(s[nt][3] * sc2);
            if (do_mask) {
                if (cg     > rg0) p0 = 0.0f;
                if (cg + 1 > rg0) p1 = 0.0f;
                if (cg     > rg1) p2 = 0.0f;
                if (cg + 1 > rg1) p3 = 0.0f;
            }
            s[nt][0] = p0; s[nt][1] = p1; s[nt][2] = p2; s[nt][3] = p3;
            l0 += p0 + p1;
            l1 += p2 + p3;
        }

        uint32_t ph[2][4], pl[2][4];
#pragma unroll
        for (int ks = 0; ks < 2; ks++) {
            pack_hilo(s[2*ks][0],   s[2*ks][1],   ph[ks][0], pl[ks][0]);
            pack_hilo(s[2*ks][2],   s[2*ks][3],   ph[ks][1], pl[ks][1]);
            pack_hilo(s[2*ks+1][0], s[2*ks+1][1], ph[ks][2], pl[ks][2]);
            pack_hilo(s[2*ks+1][2], s[2*ks+1][3], ph[ks][3], pl[ks][3]);
        }

#pragma unroll
        for (int ks = 0; ks < 2; ks++) {
            const uint32_t vrow = (uint32_t)(ks * 16) + v_rbase;
            const uint32_t vxr  = (vrow & 7) << 4;
#pragma unroll
            for (int np = 0; np < 4; np++) {
                const int g0 = 2 * np, g1 = 2 * np + 1;
                const uint32_t voffA = vrow * 256 + (((uint32_t)(g0 * 32) + v_cb) ^ vxr);
                const uint32_t voffB = vrow * 256 + (((uint32_t)(g1 * 32) + v_cb) ^ vxr);
                uint32_t va[4], vb[4], wa[4], wb[4];
                LDSM_X4_T(va[0], va[1], va[2], va[3], sb + kvb + KVO_VHI + voffA);
                LDSM_X4_T(vb[0], vb[1], vb[2], vb[3], sb + kvb + KVO_VHI + voffB);
                LDSM_X4_T(wa[0], wa[1], wa[2], wa[3], sb + kvb + KVO_VLO + voffA);
                LDSM_X4_T(wb[0], wb[1], wb[2], wb[3], sb + kvb + KVO_VLO + voffB);
                mma_bf16(o[2*g0][0], o[2*g0][1], o[2*g0][2], o[2*g0][3],
                         ph[ks][0], ph[ks][1], ph[ks][2], ph[ks][3], va[0], va[1]);
                mma_bf16(o[2*g0+1][0], o[2*g0+1][1], o[2*g0+1][2], o[2*g0+1][3],
                         ph[ks][0], ph[ks][1], ph[ks][2], ph[ks][3], va[2], va[3]);
                mma_bf16(o[2*g1][0], o[2*g1][1], o[2*g1][2], o[2*g1][3],
                         ph[ks][0], ph[ks][1], ph[ks][2], ph[ks][3], vb[0], vb[1]);
                mma_bf16(o[2*g1+1][0], o[2*g1+1][1], o[2*g1+1][2], o[2*g1+1][3],
                         ph[ks][0], ph[ks][1], ph[ks][2], ph[ks][3], vb[2], vb[3]);
                mma_bf16(o[2*g0][0], o[2*g0][1], o[2*g0][2], o[2*g0][3],
                         ph[ks][0], ph[ks][1], ph[ks][2], ph[ks][3], wa[0], wa[1]);
                mma_bf16(o[2*g0+1][0], o[2*g0+1][1], o[2*g0+1][2], o[2*g0+1][3],
                         ph[ks][0], ph[ks][1], ph[ks][2], ph[ks][3], wa[2], wa[3]);
                mma_bf16(o[2*g1][0], o[2*g1][1], o[2*g1][2], o[2*g1][3],
                         ph[ks][0], ph[ks][1], ph[ks][2], ph[ks][3], wb[0], wb[1]);
                mma_bf16(o[2*g1+1][0], o[2*g1+1][1], o[2*g1+1][2], o[2*g1+1][3],
                         ph[ks][0], ph[ks][1], ph[ks][2], ph[ks][3], wb[2], wb[3]);
                mma_bf16(o[2*g0][0], o[2*g0][1], o[2*g0][2], o[2*g0][3],
                         pl[ks][0], pl[ks][1], pl[ks][2], pl[ks][3], va[0], va[1]);
                mma_bf16(o[2*g0+1][0], o[2*g0+1][1], o[2*g0+1][2], o[2*g0+1][3],
                         pl[ks][0], pl[ks][1], pl[ks][2], pl[ks][3], va[2], va[3]);
                mma_bf16(o[2*g1][0], o[2*g1][1], o[2*g1][2], o[2*g1][3],
                         pl[ks][0], pl[ks][1], pl[ks][2], pl[ks][3], vb[0], vb[1]);
                mma_bf16(o[2*g1+1][0], o[2*g1+1][1], o[2*g1+1][2], o[2*g1+1][3],
                         pl[ks][0], pl[ks][1], pl[ks][2], pl[ks][3], vb[2], vb[3]);
            }
        }
    }

    // ---- epilogue: reduce l across quad, O /= l, write bf16 hi/lo ----
    l0 += __shfl_xor_sync(0xffffffffu, l0, 1);
    l0 += __shfl_xor_sync(0xffffffffu, l0, 2);
    l1 += __shfl_xor_sync(0xffffffffu, l1, 1);
    l1 += __shfl_xor_sync(0xffffffffu, l1, 2);
    const float inv0 = 1.0f / l0, inv1 = 1.0f / l1;
#pragma unroll
    for (int nt = 0; nt < 16; nt++) {
        const int col = h * HDIM + nt * 8 + cb;
        uint32_t hA, lA, hB, lB;
        pack_hilo(o[nt][0] * inv0, o[nt][1] * inv0, hA, lA);
        pack_hilo(o[nt][2] * inv1, o[nt][3] * inv1, hB, lB);
        *(uint32_t*)(g_ohi + (size_t)rg0 * D_MODEL + col) = hA;
        *(uint32_t*)(g_olo + (size_t)rg0 * D_MODEL + col) = lA;
        *(uint32_t*)(g_ohi + (size_t)rg1 * D_MODEL + col) = hB;
        *(uint32_t*)(g_olo + (size_t)rg1 * D_MODEL + col) = lB;
    }
}

// ---------------------------------------------------------------------------
// Launch
// ---------------------------------------------------------------------------
extern "C" void kernel_launch(void* const* d_in, const int* in_sizes, int n_in,
                              void* d_out, int out_size)
{
    const float* x  = (const float*)d_in[0];
    const float* wq = (const float*)d_in[1];
    const float* wk = (const float*)d_in[2];
    const float* wv = (const float*)d_in[3];
    const float* wo = (const float*)d_in[4];
    const int* causal = (const int*)d_in[5];
    float* out = (float*)d_out;

    __nv_bfloat16 *xhi, *xlo, *ohi, *olo;
    __nv_bfloat16 *qhi, *qlo, *khi, *klo, *vhi, *vlo;
    __nv_bfloat16 *wqh, *wql, *wkh, *wkl, *wvh, *wvl, *woh, *wol;
    cudaGetSymbolAddress((void**)&xhi, g_xhi);  cudaGetSymbolAddress((void**)&xlo, g_xlo);
    cudaGetSymbolAddress((void**)&ohi, g_ohi);  cudaGetSymbolAddress((void**)&olo, g_olo);
    cudaGetSymbolAddress((void**)&qhi, g_qhi);  cudaGetSymbolAddress((void**)&qlo, g_qlo);
    cudaGetSymbolAddress((void**)&khi, g_khi);  cudaGetSymbolAddress((void**)&klo, g_klo);
    cudaGetSymbolAddress((void**)&vhi, g_vhi);  cudaGetSymbolAddress((void**)&vlo, g_vlo);
    cudaGetSymbolAddress((void**)&wqh, g_wqhi); cudaGetSymbolAddress((void**)&wql, g_wqlo);
    cudaGetSymbolAddress((void**)&wkh, g_wkhi); cudaGetSymbolAddress((void**)&wkl, g_wklo);
    cudaGetSymbolAddress((void**)&wvh, g_wvhi); cudaGetSymbolAddress((void**)&wvl, g_wvlo);
    cudaGetSymbolAddress((void**)&woh, g_wohi); cudaGetSymbolAddress((void**)&wol, g_wolo);

    const int nx4 = S_LEN * D_MODEL / 4;
    const int nw4 = D_MODEL * D_MODEL / 4;

    split_kernel<<<nx4 / 256, 256>>>((const float4*)x, (__nv_bfloat162*)xhi, (__nv_bfloat162*)xlo, nx4);
    split_w_kernel<<<dim3(nw4 / 256, 4), 256>>>(
        (const float4*)wq, (const float4*)wk, (const float4*)wv, (const float4*)wo,
        (__nv_bfloat162*)wqh, (__nv_bfloat162*)wql,
        (__nv_bfloat162*)wkh, (__nv_bfloat162*)wkl,
        (__nv_bfloat162*)wvh, (__nv_bfloat162*)wvl,
        (__nv_bfloat162*)woh, (__nv_bfloat162*)wol, nw4);

    cudaFuncSetAttribute(gemm_mma_kernel<true>,  cudaFuncAttributeMaxDynamicSharedMemorySize, GEMM_SMEM);
    cudaFuncSetAttribute(gemm_mma_kernel<false>, cudaFuncAttributeMaxDynamicSharedMemorySize, GEMM_SMEM);
    dim3 gqkv(D_MODEL / 128, S_LEN / 128, 3);
    gemm_mma_kernel<true><<<gqkv, 256, GEMM_SMEM>>>(
        xhi, xlo, wqh, wql, wkh, wkl, wvh, wvl,
        nullptr, qhi, qlo, khi, klo, vhi, vlo);

    cudaFuncSetAttribute(attn_mma_kernel, cudaFuncAttributeMaxDynamicSharedMemorySize, ATT_SMEM);
    attn_mma_kernel<<<dim3(S_LEN / 64, NHEADS), 128, ATT_SMEM>>>(causal);

    dim3 gout(D_MODEL / 128, S_LEN / 128, 1);
    gemm_mma_kernel<false><<<gout, 256, GEMM_SMEM>>>(
        ohi, olo, woh, wol, woh, wol, woh, wol,
        out, nullptr, nullptr, nullptr, nullptr, nullptr, nullptr);
}

// round 17
// speedup vs baseline: 1.1204x; 1.0984x over previous
#include <cuda_runtime.h>
#include <cuda_bf16.h>
#include <math.h>
#include <stdint.h>

#define S_LEN   4096
#define D_MODEL 2048
#define NHEADS  16
#define HDIM    128

// ---------------------------------------------------------------------------
// Scratch (device globals: allocation-guard-safe)
// ---------------------------------------------------------------------------
__device__ __nv_bfloat16 g_xhi[S_LEN * D_MODEL];
__device__ __nv_bfloat16 g_xlo[S_LEN * D_MODEL];
__device__ __nv_bfloat16 g_qhi[S_LEN * D_MODEL];
__device__ __nv_bfloat16 g_qlo[S_LEN * D_MODEL];
__device__ __nv_bfloat16 g_khi[S_LEN * D_MODEL];
__device__ __nv_bfloat16 g_klo[S_LEN * D_MODEL];
__device__ __nv_bfloat16 g_vhi[S_LEN * D_MODEL];
__device__ __nv_bfloat16 g_vlo[S_LEN * D_MODEL];
__device__ __nv_bfloat16 g_ohi[S_LEN * D_MODEL];
__device__ __nv_bfloat16 g_olo[S_LEN * D_MODEL];
__device__ __nv_bfloat16 g_wqhi[D_MODEL * D_MODEL];
__device__ __nv_bfloat16 g_wqlo[D_MODEL * D_MODEL];
__device__ __nv_bfloat16 g_wkhi[D_MODEL * D_MODEL];
__device__ __nv_bfloat16 g_wklo[D_MODEL * D_MODEL];
__device__ __nv_bfloat16 g_wvhi[D_MODEL * D_MODEL];
__device__ __nv_bfloat16 g_wvlo[D_MODEL * D_MODEL];
__device__ __nv_bfloat16 g_wohi[D_MODEL * D_MODEL];
__device__ __nv_bfloat16 g_wolo[D_MODEL * D_MODEL];

// Cross-kernel dependency flags (reset every run by split_w_kernel)
__device__ int g_qkv_cnt[NHEADS];   // per head: target 96 (32 m-blocks x 3 tensors)
__device__ int g_attn_cnt[32];      // per 128-row block: target 32 (2 qb x 16 heads)

// ---------------------------------------------------------------------------
// Helpers
// ---------------------------------------------------------------------------
__device__ __forceinline__ uint32_t smem_u32(const void* p) {
    uint32_t a;
    asm("{ .reg .u64 t; cvta.to.shared.u64 t, %1; cvt.u32.u64 %0, t; }" : "=r"(a) : "l"(p));
    return a;
}

#define LAUNCH_DEPENDENTS() asm volatile("griddepcontrol.launch_dependents;" ::: "memory")

#define LDSM_X4(r0, r1, r2, r3, addr)                                         \
    asm volatile("ldmatrix.sync.aligned.m8n8.x4.shared.b16 {%0,%1,%2,%3}, [%4];" \
        : "=r"(r0), "=r"(r1), "=r"(r2), "=r"(r3) : "r"(addr))

#define LDSM_X4_T(r0, r1, r2, r3, addr)                                       \
    asm volatile("ldmatrix.sync.aligned.m8n8.x4.trans.shared.b16 {%0,%1,%2,%3}, [%4];" \
        : "=r"(r0), "=r"(r1), "=r"(r2), "=r"(r3) : "r"(addr))

#define CP_ASYNC16(dst, src)                                                  \
    asm volatile("cp.async.cg.shared.global [%0], [%1], 16;" :: "r"(dst), "l"(src))
#define CP_COMMIT() asm volatile("cp.async.commit_group;" ::: "memory")
#define CP_WAIT0()  asm volatile("cp.async.wait_group 0;" ::: "memory")

__device__ __forceinline__ void mma_bf16(float& c0, float& c1, float& c2, float& c3,
                                         uint32_t a0, uint32_t a1, uint32_t a2, uint32_t a3,
                                         uint32_t b0, uint32_t b1) {
    asm volatile(
        "mma.sync.aligned.m16n8k16.row.col.f32.bf16.bf16.f32 "
        "{%0,%1,%2,%3}, {%4,%5,%6,%7}, {%8,%9}, {%0,%1,%2,%3};"
        : "+f"(c0), "+f"(c1), "+f"(c2), "+f"(c3)
        : "r"(a0), "r"(a1), "r"(a2), "r"(a3), "r"(b0), "r"(b1));
}

__device__ __forceinline__ uint32_t pack2(__nv_bfloat16 a, __nv_bfloat16 b) {
    __nv_bfloat162 t(a, b);
    return *reinterpret_cast<uint32_t*>(&t);
}

__device__ __forceinline__ void pack_hilo(float x, float y, uint32_t& hi, uint32_t& lo) {
    __nv_bfloat16 hx = __float2bfloat16(x), hy = __float2bfloat16(y);
    float rx = x - __bfloat162float(hx), ry = y - __bfloat162float(hy);
    hi = pack2(hx, hy);
    lo = pack2(__float2bfloat16(rx), __float2bfloat16(ry));
}

__device__ __forceinline__ float fast_exp2(float x) {
    float r;
    asm("ex2.approx.ftz.f32 %0, %1;" : "=f"(r) : "f"(x));
    return r;
}

__device__ __forceinline__ uint32_t swz64(uint32_t off) { return off ^ ((off >> 3) & 0x30); }
__device__ __forceinline__ uint32_t vswz(uint32_t off)  { return off ^ ((off >> 4) & 0x70); }

// ---------------------------------------------------------------------------
// fp32 -> bf16 hi/lo splits
// ---------------------------------------------------------------------------
__global__ __launch_bounds__(256) void split_kernel(
    const float4* __restrict__ src, __nv_bfloat162* __restrict__ hi,
    __nv_bfloat162* __restrict__ lo, int n4)
{
    int i = blockIdx.x * blockDim.x + threadIdx.x;
    if (i >= n4) return;
    float4 v = src[i];
    uint32_t h0, l0, h1, l1;
    pack_hilo(v.x, v.y, h0, l0);
    pack_hilo(v.z, v.w, h1, l1);
    *reinterpret_cast<uint32_t*>(&hi[2 * i + 0]) = h0;
    *reinterpret_cast<uint32_t*>(&hi[2 * i + 1]) = h1;
    *reinterpret_cast<uint32_t*>(&lo[2 * i + 0]) = l0;
    *reinterpret_cast<uint32_t*>(&lo[2 * i + 1]) = l1;
}

__global__ __launch_bounds__(256) void split_w_kernel(
    const float4* __restrict__ w0, const float4* __restrict__ w1,
    const float4* __restrict__ w2, const float4* __restrict__ w3,
    __nv_bfloat162* __restrict__ h0p, __nv_bfloat162* __restrict__ l0p,
    __nv_bfloat162* __restrict__ h1p, __nv_bfloat162* __restrict__ l1p,
    __nv_bfloat162* __restrict__ h2p, __nv_bfloat162* __restrict__ l2p,
    __nv_bfloat162* __restrict__ h3p, __nv_bfloat162* __restrict__ l3p,
    int n4)
{
    // Reset cross-kernel flags for this run (one CTA; QKV waits on full kernel)
    if (blockIdx.x == 0 && blockIdx.y == 0) {
        int t = threadIdx.x;
        if (t < NHEADS) g_qkv_cnt[t] = 0;
        else if (t < NHEADS + 32) g_attn_cnt[t - NHEADS] = 0;
    }

    int i = blockIdx.x * blockDim.x + threadIdx.x;
    if (i >= n4) return;
    const int s = blockIdx.y;
    const float4* src = (s == 0) ? w0 : (s == 1) ? w1 : (s == 2) ? w2 : w3;
    __nv_bfloat162* hi = (s == 0) ? h0p : (s == 1) ? h1p : (s == 2) ? h2p : h3p;
    __nv_bfloat162* lo = (s == 0) ? l0p : (s == 1) ? l1p : (s == 2) ? l2p : l3p;
    float4 v = src[i];
    uint32_t a0, b0, a1, b1;
    pack_hilo(v.x, v.y, a0, b0);
    pack_hilo(v.z, v.w, a1, b1);
    *reinterpret_cast<uint32_t*>(&hi[2 * i + 0]) = a0;
    *reinterpret_cast<uint32_t*>(&hi[2 * i + 1]) = a1;
    *reinterpret_cast<uint32_t*>(&lo[2 * i + 0]) = b0;
    *reinterpret_cast<uint32_t*>(&lo[2 * i + 1]) = b1;
}

// ---------------------------------------------------------------------------
// bf16x3 GEMM, cp.async 2-stage (champion config).
// BF16OUT (QKV): grid (96, 16) head-major; signals g_qkv_cnt[head] at end.
// !BF16OUT (out-proj): grid (16, 32); spins on g_attn_cnt[m-block] at start.
// ---------------------------------------------------------------------------
#define GBK2      32
#define GK_ITERS2 (D_MODEL / GBK2)
#define STAGE_B   32768
#define TO_AHI    0
#define TO_ALO    8192
#define TO_BHI    16384
#define TO_BLO    24576
#define GEMM_SMEM (2 * STAGE_B)   // 65536

template<bool BF16OUT>
__global__ __launch_bounds__(256) void gemm_mma_kernel(
    const __nv_bfloat16* __restrict__ Ahi, const __nv_bfloat16* __restrict__ Alo,
    const __nv_bfloat16* __restrict__ Bhi0, const __nv_bfloat16* __restrict__ Blo0,
    const __nv_bfloat16* __restrict__ Bhi1, const __nv_bfloat16* __restrict__ Blo1,
    const __nv_bfloat16* __restrict__ Bhi2, const __nv_bfloat16* __restrict__ Blo2,
    float* __restrict__ C0,
    __nv_bfloat16* __restrict__ Chi0, __nv_bfloat16* __restrict__ Clo0,
    __nv_bfloat16* __restrict__ Chi1, __nv_bfloat16* __restrict__ Clo1,
    __nv_bfloat16* __restrict__ Chi2, __nv_bfloat16* __restrict__ Clo2)
{
    extern __shared__ char smem[];
    const uint32_t sbase = smem_u32(smem);
    const int tid  = threadIdx.x;
    const int wid  = tid >> 5;
    const int lane = tid & 31;

    int bz, m0, n0;
    if (BF16OUT) {
        // QKV: head-major completion order. x = m*3+z (96), y = head (16)
        LAUNCH_DEPENDENTS();           // let attention launch during our last wave
        bz = blockIdx.x % 3;
        m0 = (blockIdx.x / 3) * 128;
        n0 = blockIdx.y * 128;
    } else {
        // out-proj: wait for the 128 O-rows this tile consumes
        bz = 0;
        n0 = blockIdx.x * 128;
        m0 = blockIdx.y * 128;
        if (tid == 0) {
            while (atomicAdd(&g_attn_cnt[blockIdx.y], 0) < 32) __nanosleep(128);
        }
        __syncthreads();
    }

    const __nv_bfloat16* Bhi = (bz == 0) ? Bhi0 : (bz == 1) ? Bhi1 : Bhi2;
    const __nv_bfloat16* Blo = (bz == 0) ? Blo0 : (bz == 1) ? Blo1 : Blo2;
    __nv_bfloat16* Chi = (bz == 0) ? Chi0 : (bz == 1) ? Chi1 : Chi2;
    __nv_bfloat16* Clo = (bz == 0) ? Clo0 : (bz == 1) ? Clo1 : Clo2;

    const int warp_m = wid & 1;
    const int warp_n = wid >> 1;

    const int lr0 = tid >> 2;
    const int lc0 = tid & 3;

    const uint32_t a_rowpart = (uint32_t)((warp_m * 64 + (lane & 15)) * 64 + (lane >> 4) * 16);
    const uint32_t b_rowpart = (uint32_t)((warp_n * 32 + (lane & 7) + ((lane >> 4) << 3)) * 64
                                          + ((lane >> 3) & 1) * 16);

    float acc[4][4][4];
#pragma unroll
    for (int i = 0; i < 4; i++)
#pragma unroll
        for (int j = 0; j < 4; j++)
#pragma unroll
            for (int t = 0; t < 4; t++) acc[i][j][t] = 0.0f;

    auto load_stage = [&](int it, int stage) {
        const int k0 = it * GBK2;
        const uint32_t sb = sbase + stage * STAGE_B;
        const __nv_bfloat16* srcs[4] = { Ahi, Alo, Bhi, Blo };
        const uint32_t offs[4] = { TO_AHI, TO_ALO, TO_BHI, TO_BLO };
        const int rows[4] = { m0, m0, n0, n0 };
#pragma unroll
        for (int t = 0; t < 4; t++) {
#pragma unroll
            for (int i = 0; i < 2; i++) {
                int r = lr0 + i * 64;
                const void* src = srcs[t] + (size_t)(rows[t] + r) * D_MODEL + k0 + lc0 * 8;
                uint32_t dst = sb + offs[t] + swz64((uint32_t)(r * 64 + lc0 * 16));
                CP_ASYNC16(dst, src);
            }
        }
    };

    load_stage(0, 0);
    CP_COMMIT();

    for (int it = 0; it < GK_ITERS2; it++) {
        const int cur = it & 1;
        CP_WAIT0();
        __syncthreads();
        if (it + 1 < GK_ITERS2) { load_stage(it + 1, cur ^ 1); CP_COMMIT(); }

        const uint32_t sb = sbase + cur * STAGE_B;
#pragma unroll
        for (int ks = 0; ks < 2; ks++) {
            const uint32_t kbyte = (uint32_t)(ks * 32);

            uint32_t bh[8], bl[8];
            LDSM_X4(bh[0], bh[1], bh[2], bh[3], sb + TO_BHI + swz64(b_rowpart + kbyte));
            LDSM_X4(bh[4], bh[5], bh[6], bh[7], sb + TO_BHI + swz64(b_rowpart + 1024 + kbyte));
            LDSM_X4(bl[0], bl[1], bl[2], bl[3], sb + TO_BLO + swz64(b_rowpart + kbyte));
            LDSM_X4(bl[4], bl[5], bl[6], bl[7], sb + TO_BLO + swz64(b_rowpart + 1024 + kbyte));

            uint32_t af[16];
#pragma unroll
            for (int mt = 0; mt < 4; mt++) {
                uint32_t ad = sb + TO_AHI + swz64(a_rowpart + (uint32_t)(mt * 1024) + kbyte);
                LDSM_X4(af[mt * 4 + 0], af[mt * 4 + 1], af[mt * 4 + 2], af[mt * 4 + 3], ad);
            }
#pragma unroll
            for (int mt = 0; mt < 4; mt++)
#pragma unroll
                for (int nt = 0; nt < 4; nt++)
                    mma_bf16(acc[mt][nt][0], acc[mt][nt][1], acc[mt][nt][2], acc[mt][nt][3],
                             af[mt*4+0], af[mt*4+1], af[mt*4+2], af[mt*4+3],
                             bh[nt*2+0], bh[nt*2+1]);
#pragma unroll
            for (int mt = 0; mt < 4; mt++)
#pragma unroll
                for (int nt = 0; nt < 4; nt++)
                    mma_bf16(acc[mt][nt][0], acc[mt][nt][1], acc[mt][nt][2], acc[mt][nt][3],
                             af[mt*4+0], af[mt*4+1], af[mt*4+2], af[mt*4+3],
                             bl[nt*2+0], bl[nt*2+1]);
#pragma unroll
            for (int mt = 0; mt < 4; mt++) {
                uint32_t ad = sb + TO_ALO + swz64(a_rowpart + (uint32_t)(mt * 1024) + kbyte);
                LDSM_X4(af[mt * 4 + 0], af[mt * 4 + 1], af[mt * 4 + 2], af[mt * 4 + 3], ad);
            }
#pragma unroll
            for (int mt = 0; mt < 4; mt++)
#pragma unroll
                for (int nt = 0; nt < 4; nt++)
                    mma_bf16(acc[mt][nt][0], acc[mt][nt][1], acc[mt][nt][2], acc[mt][nt][3],
                             af[mt*4+0], af[mt*4+1], af[mt*4+2], af[mt*4+3],
                             bh[nt*2+0], bh[nt*2+1]);
        }
        __syncthreads();
    }

#pragma unroll
    for (int mt = 0; mt < 4; mt++) {
        int row = m0 + warp_m * 64 + mt * 16 + (lane >> 2);
#pragma unroll
        for (int nt = 0; nt < 4; nt++) {
            int col = n0 + warp_n * 32 + nt * 8 + (lane & 3) * 2;
            if (BF16OUT) {
                uint32_t h01, l01, h23, l23;
                pack_hilo(acc[mt][nt][0], acc[mt][nt][1], h01, l01);
                pack_hilo(acc[mt][nt][2], acc[mt][nt][3], h23, l23);
                *(uint32_t*)(Chi + (size_t)row * D_MODEL + col)       = h01;
                *(uint32_t*)(Clo + (size_t)row * D_MODEL + col)       = l01;
                *(uint32_t*)(Chi + (size_t)(row + 8) * D_MODEL + col) = h23;
                *(uint32_t*)(Clo + (size_t)(row + 8) * D_MODEL + col) = l23;
            } else {
                *(float2*)(C0 + (size_t)row * D_MODEL + col) =
                    make_float2(acc[mt][nt][0], acc[mt][nt][1]);
                *(float2*)(C0 + (size_t)(row + 8) * D_MODEL + col) =
                    make_float2(acc[mt][nt][2], acc[mt][nt][3]);
            }
        }
    }

    if (BF16OUT) {
        // Release: make stores visible, then signal this head's progress
        __threadfence();
        __syncthreads();
        if (tid == 0) atomicAdd(&g_qkv_cnt[blockIdx.y], 1);
    }
}

// ---------------------------------------------------------------------------
// Flash attention, bf16x3, causal (champion config).
// PDL-dependent of QKV: spins on g_qkv_cnt[head]; signals g_attn_cnt at end.
// ---------------------------------------------------------------------------
#define ATT_QHI  0
#define ATT_QLO  16384
#define ATT_KV0  32768
#define KV_STAGE 32768
#define KVO_KHI  0
#define KVO_KLO  8192
#define KVO_VHI  16384
#define KVO_VLO  24576
#define ATT_SMEM (ATT_KV0 + 2 * KV_STAGE)   // 98304

__global__ __launch_bounds__(128, 2) void attn_mma_kernel(const int* __restrict__ causal_flag)
{
    extern __shared__ char smem[];
    const uint32_t sb = smem_u32(smem);
    const int tid  = threadIdx.x;
    const int w    = tid >> 5;
    const int lane = tid & 31;
    const int q0   = (gridDim.x - 1 - blockIdx.x) * 64;
    const int h    = blockIdx.y;
    const int causal = *causal_flag;
    const float sc2 = 0.08838834764831845f * 1.4426950408889634f;  // sm_scale*log2e

    // Let out-proj launch during our last wave; then wait for this head's QKV
    LAUNCH_DEPENDENTS();
    if (tid == 0) {
        while (atomicAdd(&g_qkv_cnt[h], 0) < 96) __nanosleep(128);
    }
    __syncthreads();

    // ---- Q hi/lo -> smem ----
#pragma unroll
    for (int t = 0; t < 2; t++) {
        const __nv_bfloat16* src = t ? g_qlo : g_qhi;
        const uint32_t dst = t ? ATT_QLO : ATT_QHI;
#pragma unroll
        for (int i = 0; i < 8; i++) {
            int f = i * 128 + tid;
            int row = f >> 4, ch = f & 15;
            uint4 v = *(const uint4*)(src + (size_t)(q0 + row) * D_MODEL + h * HDIM + ch * 8);
            *(uint4*)(smem + dst + vswz((uint32_t)(row * 256 + ch * 16))) = v;
        }
    }

    const int kr0 = tid >> 4;
    const int kc0 = tid & 15;

    auto load_kv = [&](int kb, int stage) {
        const int k0 = kb * 32;
        const uint32_t base = ATT_KV0 + stage * KV_STAGE;
        const __nv_bfloat16* srcs[4] = { g_khi, g_klo, g_vhi, g_vlo };
        const uint32_t offs[4] = { KVO_KHI, KVO_KLO, KVO_VHI, KVO_VLO };
#pragma unroll
        for (int t = 0; t < 4; t++) {
#pragma unroll
            for (int i = 0; i < 4; i++) {
                int row = kr0 + i * 8;
                const void* src = srcs[t] + (size_t)(k0 + row) * D_MODEL + h * HDIM + kc0 * 8;
                uint32_t dst = sb + base + offs[t] + vswz((uint32_t)(row * 256 + kc0 * 16));
                CP_ASYNC16(dst, src);
            }
        }
    };

    load_kv(0, 0);
    CP_COMMIT();

    const int rq  = lane >> 2;
    const int cb  = (lane & 3) * 2;
    const int rg0 = q0 + w * 16 + rq;
    const int rg1 = rg0 + 8;

    const uint32_t a_row = (uint32_t)(w * 16 + (lane & 15));
    const uint32_t a_xr  = (a_row & 7) << 4;
    const uint32_t a_cb  = ((lane >> 4) & 1) * 16;
    const uint32_t k_rbase = ((lane >> 4) & 1) * 8 + (lane & 7);
    const uint32_t k_cb    = ((lane >> 3) & 1) * 16;
    const uint32_t v_rbase = ((lane >> 3) & 1) * 8 + (lane & 7);
    const uint32_t v_cb    = ((lane >> 4) & 1) * 16;

    __syncthreads();
    uint32_t qh[8][4];
#pragma unroll
    for (int ks = 0; ks < 8; ks++) {
        const uint32_t aoff = a_row * 256 + (((uint32_t)(ks * 32) + a_cb) ^ a_xr);
        LDSM_X4(qh[ks][0], qh[ks][1], qh[ks][2], qh[ks][3], sb + ATT_QHI + aoff);
    }

    float o[16][4];
#pragma unroll
    for (int i = 0; i < 16; i++)
#pragma unroll
        for (int t = 0; t < 4; t++) o[i][t] = 0.0f;
    float l0 = 0.0f, l1 = 0.0f;

    const int kb_max = causal ? (q0 + 63) / 32 : (S_LEN / 32 - 1);

    for (int kb = 0; kb <= kb_max; kb++) {
        const int k0 = kb * 32;
        const int cur = kb & 1;
        CP_WAIT0();
        __syncthreads();
        if (kb + 1 <= kb_max) { load_kv(kb + 1, cur ^ 1); CP_COMMIT(); }

        const uint32_t kvb = ATT_KV0 + cur * KV_STAGE;

        float s[4][4];
#pragma unroll
        for (int i = 0; i < 4; i++)
#pragma unroll
            for (int t = 0; t < 4; t++) s[i][t] = 0.0f;

#pragma unroll
        for (int ks = 0; ks < 8; ks++) {
            const uint32_t aoff = a_row * 256 + (((uint32_t)(ks * 32) + a_cb) ^ a_xr);
            uint32_t al0, al1, al2, al3;
            LDSM_X4(al0, al1, al2, al3, sb + ATT_QLO + aoff);

            uint32_t bh[8], bl[8];
#pragma unroll
            for (int ng = 0; ng < 2; ng++) {
                const uint32_t krow = (uint32_t)(ng * 16) + k_rbase;
                const uint32_t koff = krow * 256 + (((uint32_t)(ks * 32) + k_cb) ^ ((krow & 7) << 4));
                LDSM_X4(bh[4*ng+0], bh[4*ng+1], bh[4*ng+2], bh[4*ng+3], sb + kvb + KVO_KHI + koff);
                LDSM_X4(bl[4*ng+0], bl[4*ng+1], bl[4*ng+2], bl[4*ng+3], sb + kvb + KVO_KLO + koff);
            }
#pragma unroll
            for (int ng = 0; ng < 2; ng++) {
                mma_bf16(s[2*ng][0], s[2*ng][1], s[2*ng][2], s[2*ng][3],
                         qh[ks][0], qh[ks][1], qh[ks][2], qh[ks][3], bh[4*ng+0], bh[4*ng+1]);
                mma_bf16(s[2*ng+1][0], s[2*ng+1][1], s[2*ng+1][2], s[2*ng+1][3],
                         qh[ks][0], qh[ks][1], qh[ks][2], qh[ks][3], bh[4*ng+2], bh[4*ng+3]);
            }
#pragma unroll
            for (int ng = 0; ng < 2; ng++) {
                mma_bf16(s[2*ng][0], s[2*ng][1], s[2*ng][2], s[2*ng][3],
                         qh[ks][0], qh[ks][1], qh[ks][2], qh[ks][3], bl[4*ng+0], bl[4*ng+1]);
                mma_bf16(s[2*ng+1][0], s[2*ng+1][1], s[2*ng+1][2], s[2*ng+1][3],
                         qh[ks][0], qh[ks][1], qh[ks][2], qh[ks][3], bl[4*ng+2], bl[4*ng+3]);
            }
#pragma unroll
            for (int ng = 0; ng < 2; ng++) {
                mma_bf16(s[2*ng][0], s[2*ng][1], s[2*ng][2], s[2*ng][3],
                         al0, al1, al2, al3, bh[4*ng+0], bh[4*ng+1]);
                mma_bf16(s[2*ng+1][0], s[2*ng+1][1], s[2*ng+1][2], s[2*ng+1][3],
                         al0, al1, al2, al3, bh[4*ng+2], bh[4*ng+3]);
            }
        }

        const bool do_mask = (causal != 0) && (k0 + 31 > q0);
#pragma unroll
        for (int nt = 0; nt < 4; nt++) {
            const int cg = k0 + nt * 8 + cb;
            float p0 = fast_exp2(s[nt][0] * sc2);
            float p1 = fast_exp2(s[nt][1] * sc2);
            float p2 = fast_exp2(s[nt][2] * sc2);
            float p3 = fast_exp2(s[nt][3] * sc2);
            if (do_mask) {
                if (cg     > rg0) p0 = 0.0f;
                if (cg + 1 > rg0) p1 = 0.0f;
                if (cg     > rg1) p2 = 0.0f;
                if (cg + 1 > rg1) p3 = 0.0f;
            }
            s[nt][0] = p0; s[nt][1] = p1; s[nt][2] = p2; s[nt][3] = p3;
            l0 += p0 + p1;
            l1 += p2 + p3;
        }

        uint32_t ph[2][4], pl[2][4];
#pragma unroll
        for (int ks = 0; ks < 2; ks++) {
            pack_hilo(s[2*ks][0],   s[2*ks][1],   ph[ks][0], pl[ks][0]);
            pack_hilo(s[2*ks][2],   s[2*ks][3],   ph[ks][1], pl[ks][1]);
            pack_hilo(s[2*ks+1][0], s[2*ks+1][1], ph[ks][2], pl[ks][2]);
            pack_hilo(s[2*ks+1][2], s[2*ks+1][3], ph[ks][3], pl[ks][3]);
        }

#pragma unroll
        for (int ks = 0; ks < 2; ks++) {
            const uint32_t vrow = (uint32_t)(ks * 16) + v_rbase;
            const uint32_t vxr  = (vrow & 7) << 4;
#pragma unroll
            for (int np = 0; np < 4; np++) {
                const int g0 = 2 * np, g1 = 2 * np + 1;
                const uint32_t voffA = vrow * 256 + (((uint32_t)(g0 * 32) + v_cb) ^ vxr);
                const uint32_t voffB = vrow * 256 + (((uint32_t)(g1 * 32) + v_cb) ^ vxr);
                uint32_t va[4], vb[4], wa[4], wb[4];
                LDSM_X4_T(va[0], va[1], va[2], va[3], sb + kvb + KVO_VHI + voffA);
                LDSM_X4_T(vb[0], vb[1], vb[2], vb[3], sb + kvb + KVO_VHI + voffB);
                LDSM_X4_T(wa[0], wa[1], wa[2], wa[3], sb + kvb + KVO_VLO + voffA);
                LDSM_X4_T(wb[0], wb[1], wb[2], wb[3], sb + kvb + KVO_VLO + voffB);
                mma_bf16(o[2*g0][0], o[2*g0][1], o[2*g0][2], o[2*g0][3],
                         ph[ks][0], ph[ks][1], ph[ks][2], ph[ks][3], va[0], va[1]);
                mma_bf16(o[2*g0+1][0], o[2*g0+1][1], o[2*g0+1][2], o[2*g0+1][3],
                         ph[ks][0], ph[ks][1], ph[ks][2], ph[ks][3], va[2], va[3]);
                mma_bf16(o[2*g1][0], o[2*g1][1], o[2*g1][2], o[2*g1][3],
                         ph[ks][0], ph[ks][1], ph[ks][2], ph[ks][3], vb[0], vb[1]);
                mma_bf16(o[2*g1+1][0], o[2*g1+1][1], o[2*g1+1][2], o[2*g1+1][3],
                         ph[ks][0], ph[ks][1], ph[ks][2], ph[ks][3], vb[2], vb[3]);
                mma_bf16(o[2*g0][0], o[2*g0][1], o[2*g0][2], o[2*g0][3],
                         ph[ks][0], ph[ks][1], ph[ks][2], ph[ks][3], wa[0], wa[1]);
                mma_bf16(o[2*g0+1][0], o[2*g0+1][1], o[2*g0+1][2], o[2*g0+1][3],
                         ph[ks][0], ph[ks][1], ph[ks][2], ph[ks][3], wa[2], wa[3]);
                mma_bf16(o[2*g1][0], o[2*g1][1], o[2*g1][2], o[2*g1][3],
                         ph[ks][0], ph[ks][1], ph[ks][2], ph[ks][3], wb[0], wb[1]);
                mma_bf16(o[2*g1+1][0], o[2*g1+1][1], o[2*g1+1][2], o[2*g1+1][3],
                         ph[ks][0], ph[ks][1], ph[ks][2], ph[ks][3], wb[2], wb[3]);
                mma_bf16(o[2*g0][0], o[2*g0][1], o[2*g0][2], o[2*g0][3],
                         pl[ks][0], pl[ks][1], pl[ks][2], pl[ks][3], va[0], va[1]);
                mma_bf16(o[2*g0+1][0], o[2*g0+1][1], o[2*g0+1][2], o[2*g0+1][3],
                         pl[ks][0], pl[ks][1], pl[ks][2], pl[ks][3], va[2], va[3]);
                mma_bf16(o[2*g1][0], o[2*g1][1], o[2*g1][2], o[2*g1][3],
                         pl[ks][0], pl[ks][1], pl[ks][2], pl[ks][3], vb[0], vb[1]);
                mma_bf16(o[2*g1+1][0], o[2*g1+1][1], o[2*g1+1][2], o[2*g1+1][3],
                         pl[ks][0], pl[ks][1], pl[ks][2], pl[ks][3], vb[2], vb[3]);
            }
        }
    }

    // ---- epilogue ----
    l0 += __shfl_xor_sync(0xffffffffu, l0, 1);
    l0 += __shfl_xor_sync(0xffffffffu, l0, 2);
    l1 += __shfl_xor_sync(0xffffffffu, l1, 1);
    l1 += __shfl_xor_sync(0xffffffffu, l1, 2);
    const float inv0 = 1.0f / l0, inv1 = 1.0f / l1;
#pragma unroll
    for (int nt = 0; nt < 16; nt++) {
        const int col = h * HDIM + nt * 8 + cb;
        uint32_t hA, lA, hB, lB;
        pack_hilo(o[nt][0] * inv0, o[nt][1] * inv0, hA, lA);
        pack_hilo(o[nt][2] * inv1, o[nt][3] * inv1, hB, lB);
        *(uint32_t*)(g_ohi + (size_t)rg0 * D_MODEL + col) = hA;
        *(uint32_t*)(g_olo + (size_t)rg0 * D_MODEL + col) = lA;
        *(uint32_t*)(g_ohi + (size_t)rg1 * D_MODEL + col) = hB;
        *(uint32_t*)(g_olo + (size_t)rg1 * D_MODEL + col) = lB;
    }

    // Release: signal the 128-row block this CTA contributed to
    __threadfence();
    __syncthreads();
    if (tid == 0) atomicAdd(&g_attn_cnt[q0 >> 7], 1);
}

// ---------------------------------------------------------------------------
// Launch
// ---------------------------------------------------------------------------
extern "C" void kernel_launch(void* const* d_in, const int* in_sizes, int n_in,
                              void* d_out, int out_size)
{
    const float* x  = (const float*)d_in[0];
    const float* wq = (const float*)d_in[1];
    const float* wk = (const float*)d_in[2];
    const float* wv = (const float*)d_in[3];
    const float* wo = (const float*)d_in[4];
    const int* causal = (const int*)d_in[5];
    float* out = (float*)d_out;

    __nv_bfloat16 *xhi, *xlo, *ohi, *olo;
    __nv_bfloat16 *qhi, *qlo, *khi, *klo, *vhi, *vlo;
    __nv_bfloat16 *wqh, *wql, *wkh, *wkl, *wvh, *wvl, *woh, *wol;
    cudaGetSymbolAddress((void**)&xhi, g_xhi);  cudaGetSymbolAddress((void**)&xlo, g_xlo);
    cudaGetSymbolAddress((void**)&ohi, g_ohi);  cudaGetSymbolAddress((void**)&olo, g_olo);
    cudaGetSymbolAddress((void**)&qhi, g_qhi);  cudaGetSymbolAddress((void**)&qlo, g_qlo);
    cudaGetSymbolAddress((void**)&khi, g_khi);  cudaGetSymbolAddress((void**)&klo, g_klo);
    cudaGetSymbolAddress((void**)&vhi, g_vhi);  cudaGetSymbolAddress((void**)&vlo, g_vlo);
    cudaGetSymbolAddress((void**)&wqh, g_wqhi); cudaGetSymbolAddress((void**)&wql, g_wqlo);
    cudaGetSymbolAddress((void**)&wkh, g_wkhi); cudaGetSymbolAddress((void**)&wkl, g_wklo);
    cudaGetSymbolAddress((void**)&wvh, g_wvhi); cudaGetSymbolAddress((void**)&wvl, g_wvlo);
    cudaGetSymbolAddress((void**)&woh, g_wohi); cudaGetSymbolAddress((void**)&wol, g_wolo);

    const int nx4 = S_LEN * D_MODEL / 4;
    const int nw4 = D_MODEL * D_MODEL / 4;

    split_kernel<<<nx4 / 256, 256>>>((const float4*)x, (__nv_bfloat162*)xhi, (__nv_bfloat162*)xlo, nx4);
    split_w_kernel<<<dim3(nw4 / 256, 4), 256>>>(
        (const float4*)wq, (const float4*)wk, (const float4*)wv, (const float4*)wo,
        (__nv_bfloat162*)wqh, (__nv_bfloat162*)wql,
        (__nv_bfloat162*)wkh, (__nv_bfloat162*)wkl,
        (__nv_bfloat162*)wvh, (__nv_bfloat162*)wvl,
        (__nv_bfloat162*)woh, (__nv_bfloat162*)wol, nw4);

    cudaFuncSetAttribute(gemm_mma_kernel<true>,  cudaFuncAttributeMaxDynamicSharedMemorySize, GEMM_SMEM);
    cudaFuncSetAttribute(gemm_mma_kernel<false>, cudaFuncAttributeMaxDynamicSharedMemorySize, GEMM_SMEM);
    cudaFuncSetAttribute(attn_mma_kernel, cudaFuncAttributeMaxDynamicSharedMemorySize, ATT_SMEM);

    // QKV projections: head-major grid (x = m*3+z, y = head)
    gemm_mma_kernel<true><<<dim3(96, 16), 256, GEMM_SMEM>>>(
        xhi, xlo, wqh, wql, wkh, wkl, wvh, wvl,
        nullptr, qhi, qlo, khi, klo, vhi, vlo);

    // Attention: PDL-dependent of QKV (launches during QKV's final wave;
    // per-head readiness enforced by g_qkv_cnt flags)
    {
        cudaLaunchConfig_t cfg = {};
        cfg.gridDim = dim3(S_LEN / 64, NHEADS);
        cfg.blockDim = dim3(128);
        cfg.dynamicSmemBytes = ATT_SMEM;
        cfg.stream = 0;
        cudaLaunchAttribute attrs[1];
        attrs[0].id = cudaLaunchAttributeProgrammaticStreamSerialization;
        attrs[0].val.programmaticStreamSerializationAllowed = 1;
        cfg.attrs = attrs;
        cfg.numAttrs = 1;
        cudaLaunchKernelEx(&cfg, attn_mma_kernel, causal);
    }

    // Output projection: PDL-dependent of attention (launches during its final
    // wave; per-row-block readiness enforced by g_attn_cnt flags)
    {
        cudaLaunchConfig_t cfg = {};
        cfg.gridDim = dim3(D_MODEL / 128, S_LEN / 128);
        cfg.blockDim = dim3(256);
        cfg.dynamicSmemBytes = GEMM_SMEM;
        cfg.stream = 0;
        cudaLaunchAttribute attrs[1];
        attrs[0].id = cudaLaunchAttributeProgrammaticStreamSerialization;
        attrs[0].val.programmaticStreamSerializationAllowed = 1;
        cfg.attrs = attrs;
        cfg.numAttrs = 1;
        cudaLaunchKernelEx(&cfg, gemm_mma_kernel<false>,
            (const __nv_bfloat16*)ohi, (const __nv_bfloat16*)olo,
            (const __nv_bfloat16*)woh, (const __nv_bfloat16*)wol,
            (const __nv_bfloat16*)woh, (const __nv_bfloat16*)wol,
            (const __nv_bfloat16*)woh, (const __nv_bfloat16*)wol,
            out,
            (__nv_bfloat16*)nullptr, (__nv_bfloat16*)nullptr,
            (__nv_bfloat16*)nullptr, (__nv_bfloat16*)nullptr,
            (__nv_bfloat16*)nullptr, (__nv_bfloat16*)nullptr);
    }
}